// round 9
// baseline (speedup 1.0000x reference)
#include <cuda_runtime.h>
#include <cuda_bf16.h>
#include <cstdint>

#define N_SRC0 100000
#define N_DST0 20000
#define N_DST1 4000
#define E0V 640000
#define E1V 128000
#define IN_F 512
#define HID_F 512
#define OUT_F 256

// ---------------- scratch (device globals) ----------------------------------
__device__ float g_agg0[(size_t)N_DST0 * IN_F];
__device__ float g_h1[(size_t)N_DST0 * HID_F];
__device__ float g_agg1[(size_t)N_DST1 * HID_F];

// count layout: [C_SRC0 (100000) | C_DST1 (4000) | C_DST0 (20000) | C_SRC1 (20000)]
// then cursors. The first 104000 (src0|dst1) are scanned together.
#define OFF_C_SRC0 0
#define OFF_C_DST1 100000
#define OFF_C_DST0 104000
#define OFF_C_SRC1 124000
#define N_CNT      144000
#define OFF_CUR0   144000
#define OFF_CUR1   244000
#define N_INTS     248000
#define N_SCAN     104000
__device__ int g_ints[N_INTS];
__device__ float g_norm[N_CNT];      // rsqrt(max(cnt,1)) of the same layout

__device__ int g_rpc[N_SCAN + 1];    // combined rowptr: [0..100000]=rp0, [100000..104000]=rp1+E0V
__device__ int g_col0[E0V];
__device__ int g_col1[E1V];
__device__ int g_part[256];

// ---------------- utility kernels -------------------------------------------

__global__ void k_zero2(float4* __restrict__ a, int n4, int* __restrict__ b, int nb) {
    int stride = gridDim.x * blockDim.x;
    for (int i = blockIdx.x * blockDim.x + threadIdx.x; i < n4; i += stride)
        a[i] = make_float4(0.f, 0.f, 0.f, 0.f);
    for (int i = blockIdx.x * blockDim.x + threadIdx.x; i < nb; i += stride)
        b[i] = 0;
}

__global__ void k_count(const int* __restrict__ s0, const int* __restrict__ d0,
                        const int* __restrict__ s1, const int* __restrict__ d1,
                        int* __restrict__ ints) {
    int i = blockIdx.x * blockDim.x + threadIdx.x;
    if (i < E0V) {
        atomicAdd(ints + OFF_C_SRC0 + s0[i], 1);
        atomicAdd(ints + OFF_C_DST0 + d0[i], 1);
    } else {
        int j = i - E0V;
        if (j < E1V) {
            atomicAdd(ints + OFF_C_SRC1 + s1[j], 1);
            atomicAdd(ints + OFF_C_DST1 + d1[j], 1);
        }
    }
}

// warp-shuffle block scan (1024 threads)
__global__ void k_scan1(const int* __restrict__ cnt, int* __restrict__ rp,
                        int* __restrict__ part, int n) {
    __shared__ int ws[32];
    int tid = threadIdx.x;
    int lane = tid & 31, warp = tid >> 5;
    int i = blockIdx.x * 1024 + tid;
    int s = (i < n) ? cnt[i] : 0;
#pragma unroll
    for (int d = 1; d < 32; d <<= 1) {
        int t = __shfl_up_sync(0xffffffffu, s, d);
        if (lane >= d) s += t;
    }
    if (lane == 31) ws[warp] = s;
    __syncthreads();
    if (warp == 0) {
        int w = ws[lane];
#pragma unroll
        for (int d = 1; d < 32; d <<= 1) {
            int t = __shfl_up_sync(0xffffffffu, w, d);
            if (lane >= d) w += t;
        }
        ws[lane] = w;
    }
    __syncthreads();
    if (warp > 0) s += ws[warp - 1];
    if (i < n) rp[i + 1] = s;
    if (tid == 1023) part[blockIdx.x] = s;
}

__global__ void k_scan2(int* __restrict__ part, int nb, int* __restrict__ rp) {
    __shared__ int sd[128];
    int tid = threadIdx.x;
    sd[tid] = (tid < nb) ? part[tid] : 0;
    __syncthreads();
#pragma unroll
    for (int d = 1; d < 128; d <<= 1) {
        int t = (tid >= d) ? sd[tid - d] : 0;
        __syncthreads();
        sd[tid] += t;
        __syncthreads();
    }
    if (tid < nb) part[tid] = (tid == 0) ? 0 : sd[tid - 1];
    if (tid == 0) rp[0] = 0;
}

__global__ void k_scan3(int* __restrict__ rp, const int* __restrict__ part, int n) {
    int b = blockIdx.x;
    if (b == 0) return;
    int i = b * 1024 + threadIdx.x;
    if (i < n) rp[i + 1] += part[b];
}

// fused: norms (first N_CNT lanes) + both CSR fills
__global__ void k_fill_norm(const int* __restrict__ src0, const int* __restrict__ dst0,
                            const int* __restrict__ src1, const int* __restrict__ dst1,
                            const int* __restrict__ rpc, int* __restrict__ ints,
                            int* __restrict__ col0, int* __restrict__ col1,
                            float* __restrict__ nrm) {
    int i = blockIdx.x * blockDim.x + threadIdx.x;
    if (i < N_CNT) nrm[i] = rsqrtf(fmaxf((float)ints[i], 1.0f));
    if (i < E0V) {
        int k = src0[i];
        int pos = rpc[k] + atomicAdd(ints + OFF_CUR0 + k, 1);
        col0[pos] = dst0[i];
    } else {
        int j = i - E0V;
        if (j < E1V) {
            int k = dst1[j];
            int pos = rpc[OFF_C_DST1 + k] - E0V + atomicAdd(ints + OFF_CUR1 + k, 1);
            col1[pos] = src1[j];
        }
    }
}

// ---------------- layer-1: CSR-by-src scatter --------------------------------
__global__ void k_scatter_src(const float* __restrict__ x,
                              const int* __restrict__ rp, const int* __restrict__ col,
                              const float* __restrict__ outn,
                              float* __restrict__ agg, int n_src) {
    int w = (blockIdx.x * blockDim.x + threadIdx.x) >> 5;
    int lane = threadIdx.x & 31;
    if (w >= n_src) return;
    int beg = rp[w], end = rp[w + 1];
    if (beg == end) return;
    float sc = outn[w];
    const float4* xp = reinterpret_cast<const float4*>(x) + (size_t)w * (IN_F / 4) + lane;
    float4 v0 = xp[0], v1 = xp[32], v2 = xp[64], v3 = xp[96];
    v0.x *= sc; v0.y *= sc; v0.z *= sc; v0.w *= sc;
    v1.x *= sc; v1.y *= sc; v1.z *= sc; v1.w *= sc;
    v2.x *= sc; v2.y *= sc; v2.z *= sc; v2.w *= sc;
    v3.x *= sc; v3.y *= sc; v3.z *= sc; v3.w *= sc;
    for (int e = beg; e < end; e++) {
        int d = __ldg(col + e);
        float* ap = agg + (size_t)d * IN_F + lane * 4;
        asm volatile("red.global.add.v4.f32 [%0], {%1, %2, %3, %4};"
                     :: "l"(ap), "f"(v0.x), "f"(v0.y), "f"(v0.z), "f"(v0.w) : "memory");
        asm volatile("red.global.add.v4.f32 [%0], {%1, %2, %3, %4};"
                     :: "l"(ap + 128), "f"(v1.x), "f"(v1.y), "f"(v1.z), "f"(v1.w) : "memory");
        asm volatile("red.global.add.v4.f32 [%0], {%1, %2, %3, %4};"
                     :: "l"(ap + 256), "f"(v2.x), "f"(v2.y), "f"(v2.z), "f"(v2.w) : "memory");
        asm volatile("red.global.add.v4.f32 [%0], {%1, %2, %3, %4};"
                     :: "l"(ap + 384), "f"(v3.x), "f"(v3.y), "f"(v3.z), "f"(v3.w) : "memory");
    }
}

// ---------------- layer-2: CSR-by-dst gather ---------------------------------
__global__ void k_gather_dst(const float* __restrict__ h,
                             const int* __restrict__ rp1, const int* __restrict__ col,
                             const float* __restrict__ outn,
                             float* __restrict__ agg, int n_dst) {
    int w = (blockIdx.x * blockDim.x + threadIdx.x) >> 5;
    int lane = threadIdx.x & 31;
    if (w >= n_dst) return;
    int beg = rp1[w] - E0V, end = rp1[w + 1] - E0V;
    float4 a0 = make_float4(0.f, 0.f, 0.f, 0.f);
    float4 a1 = a0, a2 = a0, a3 = a0;
    for (int e = beg; e < end; e++) {
        int s = __ldg(col + e);
        float sc = __ldg(outn + s);
        const float4* hp = reinterpret_cast<const float4*>(h) + (size_t)s * (HID_F / 4) + lane;
        float4 v0 = __ldg(hp), v1 = __ldg(hp + 32), v2 = __ldg(hp + 64), v3 = __ldg(hp + 96);
        a0.x = fmaf(v0.x, sc, a0.x); a0.y = fmaf(v0.y, sc, a0.y);
        a0.z = fmaf(v0.z, sc, a0.z); a0.w = fmaf(v0.w, sc, a0.w);
        a1.x = fmaf(v1.x, sc, a1.x); a1.y = fmaf(v1.y, sc, a1.y);
        a1.z = fmaf(v1.z, sc, a1.z); a1.w = fmaf(v1.w, sc, a1.w);
        a2.x = fmaf(v2.x, sc, a2.x); a2.y = fmaf(v2.y, sc, a2.y);
        a2.z = fmaf(v2.z, sc, a2.z); a2.w = fmaf(v2.w, sc, a2.w);
        a3.x = fmaf(v3.x, sc, a3.x); a3.y = fmaf(v3.y, sc, a3.y);
        a3.z = fmaf(v3.z, sc, a3.z); a3.w = fmaf(v3.w, sc, a3.w);
    }
    float4* ap = reinterpret_cast<float4*>(agg) + (size_t)w * (HID_F / 4) + lane;
    ap[0] = a0; ap[32] = a1; ap[64] = a2; ap[96] = a3;
}

// ---------------- fused fp32->bf16-split HMMA GEMM, 64x128 tile --------------
// 256 thr = 8 warps (2x4), warp tile 32x32; 2 CTAs/SM. Double-buffered SMEM.
#define PADK 40
#define PADN 136
#define SZ_A (64 * PADK * 2)               // 5120
#define SZ_B (32 * PADN * 2)               // 8704
#define STAGE_BYTES (2 * SZ_A + 2 * SZ_B)  // 27648
#define GSM_TOTAL (2 * STAGE_BYTES)        // 55296
#define O_AH 0
#define O_AL SZ_A
#define O_BH (2 * SZ_A)
#define O_BL (2 * SZ_A + SZ_B)

__device__ __forceinline__ void ldm4(uint32_t* f, uint32_t addr) {
    asm volatile("ldmatrix.sync.aligned.m8n8.x4.shared.b16 {%0,%1,%2,%3}, [%4];"
                 : "=r"(f[0]), "=r"(f[1]), "=r"(f[2]), "=r"(f[3]) : "r"(addr));
}
__device__ __forceinline__ void ldm4t(uint32_t* f, uint32_t addr) {
    asm volatile("ldmatrix.sync.aligned.m8n8.x4.trans.shared.b16 {%0,%1,%2,%3}, [%4];"
                 : "=r"(f[0]), "=r"(f[1]), "=r"(f[2]), "=r"(f[3]) : "r"(addr));
}
__device__ __forceinline__ void mma16816(float* c, const uint32_t* a, const uint32_t* b) {
    asm volatile("mma.sync.aligned.m16n8k16.row.col.f32.bf16.bf16.f32 "
                 "{%0,%1,%2,%3}, {%4,%5,%6,%7}, {%8,%9}, {%0,%1,%2,%3};"
                 : "+f"(c[0]), "+f"(c[1]), "+f"(c[2]), "+f"(c[3])
                 : "r"(a[0]), "r"(a[1]), "r"(a[2]), "r"(a[3]), "r"(b[0]), "r"(b[1]));
}
__device__ __forceinline__ void cvt_hilo(float4 v, uint2& h, uint2& l) {
    __nv_bfloat16 hx = __float2bfloat16(v.x), hy = __float2bfloat16(v.y);
    __nv_bfloat16 hz = __float2bfloat16(v.z), hw = __float2bfloat16(v.w);
    __nv_bfloat162 h0(hx, hy), h1(hz, hw);
    __nv_bfloat162 l0(__float2bfloat16(v.x - __bfloat162float(hx)),
                      __float2bfloat16(v.y - __bfloat162float(hy)));
    __nv_bfloat162 l1(__float2bfloat16(v.z - __bfloat162float(hz)),
                      __float2bfloat16(v.w - __bfloat162float(hw)));
    h.x = *reinterpret_cast<uint32_t*>(&h0);
    h.y = *reinterpret_cast<uint32_t*>(&h1);
    l.x = *reinterpret_cast<uint32_t*>(&l0);
    l.y = *reinterpret_cast<uint32_t*>(&l1);
}

__global__ __launch_bounds__(256, 2) void k_gemm_f(
    const float* __restrict__ A, const float* __restrict__ rs,
    const float* __restrict__ W, const float* __restrict__ bias,
    float* __restrict__ C, int M, int Nt) {
    extern __shared__ char smem[];
    int tid = threadIdx.x;
    int wid = tid >> 5, lane = tid & 31;
    int wm = (wid >> 2) * 32;               // 0 / 32
    int wn = (wid & 3) * 32;                // 0..96
    int row0 = blockIdx.y * 64, col0 = blockIdx.x * 128;

    // A staging: row sr (0..63), 8-col group; 2 float4 per thread
    int sr = tid >> 2;
    int sk = (tid & 3) * 8;
    int rowA = row0 + sr;
    bool aval = rowA < M;
    float scA = aval ? __ldg(rs + rowA) : 0.f;
    const float* gA = A + (size_t)(aval ? rowA : 0) * 512 + sk;
    // B staging: k row bk (0..31), 16-wide n group; 4 float4 per thread
    int bk = tid >> 3;
    int bn = (tid & 7) * 16;
    const float* gW = W + (size_t)bk * Nt + col0 + bn;

    uint32_t ubase = (uint32_t)__cvta_generic_to_shared(smem);

    int aRow = wm + (lane & 15);
    int aCol = (lane >> 4) << 3;
    int kIdx = (lane & 7) + (((lane >> 3) & 1) << 3);
    int nOff = (lane >> 4) << 3;

    float acc[2][4][4];
#pragma unroll
    for (int i = 0; i < 2; i++)
#pragma unroll
        for (int j = 0; j < 4; j++)
#pragma unroll
            for (int k = 0; k < 4; k++) acc[i][j][k] = 0.f;

    // stage chunk 0 -> buffer 0
    {
        char* st = smem;
#pragma unroll
        for (int j = 0; j < 2; j++) {
            float4 va = aval ? __ldg((const float4*)(gA + 4 * j)) : make_float4(0, 0, 0, 0);
            va.x *= scA; va.y *= scA; va.z *= scA; va.w *= scA;
            uint2 h, l;
            cvt_hilo(va, h, l);
            int off = sr * PADK + sk + 4 * j;
            *(uint2*)(st + O_AH + off * 2) = h;
            *(uint2*)(st + O_AL + off * 2) = l;
        }
#pragma unroll
        for (int j = 0; j < 4; j++) {
            float4 vb = __ldg((const float4*)(gW + 4 * j));
            uint2 h, l;
            cvt_hilo(vb, h, l);
            int off = bk * PADN + bn + 4 * j;
            *(uint2*)(st + O_BH + off * 2) = h;
            *(uint2*)(st + O_BL + off * 2) = l;
        }
    }
    __syncthreads();

    for (int c = 0; c < 16; c++) {
        uint32_t ub = ubase + (c & 1) * STAGE_BYTES;

#pragma unroll
        for (int ks = 0; ks < 32; ks += 16) {
            uint32_t ah[2][4], al[2][4], bh[4][2], bl[4][2];
#pragma unroll
            for (int mt = 0; mt < 2; mt++) {
                uint32_t off = ((uint32_t)((aRow + mt * 16) * PADK + ks + aCol)) * 2;
                ldm4(ah[mt], ub + O_AH + off);
                ldm4(al[mt], ub + O_AL + off);
            }
#pragma unroll
            for (int ntp = 0; ntp < 2; ntp++) {
                uint32_t off = ((uint32_t)((ks + kIdx) * PADN + wn + ntp * 16 + nOff)) * 2;
                uint32_t t[4];
                ldm4t(t, ub + O_BH + off);
                bh[ntp * 2][0] = t[0]; bh[ntp * 2][1] = t[1];
                bh[ntp * 2 + 1][0] = t[2]; bh[ntp * 2 + 1][1] = t[3];
                ldm4t(t, ub + O_BL + off);
                bl[ntp * 2][0] = t[0]; bl[ntp * 2][1] = t[1];
                bl[ntp * 2 + 1][0] = t[2]; bl[ntp * 2 + 1][1] = t[3];
            }
#pragma unroll
            for (int mt = 0; mt < 2; mt++)
#pragma unroll
                for (int nt = 0; nt < 4; nt++) {
                    mma16816(acc[mt][nt], ah[mt], bh[nt]);
                    mma16816(acc[mt][nt], ah[mt], bl[nt]);
                    mma16816(acc[mt][nt], al[mt], bh[nt]);
                }
        }

        if (c < 15) {       // load+convert+store next chunk into other buffer
            char* st = smem + ((c & 1) ^ 1) * STAGE_BYTES;
            int ka = (c + 1) * 32;
#pragma unroll
            for (int j = 0; j < 2; j++) {
                float4 va = aval ? __ldg((const float4*)(gA + ka + 4 * j))
                                 : make_float4(0, 0, 0, 0);
                va.x *= scA; va.y *= scA; va.z *= scA; va.w *= scA;
                uint2 h, l;
                cvt_hilo(va, h, l);
                int off = sr * PADK + sk + 4 * j;
                *(uint2*)(st + O_AH + off * 2) = h;
                *(uint2*)(st + O_AL + off * 2) = l;
            }
#pragma unroll
            for (int j = 0; j < 4; j++) {
                float4 vb = __ldg((const float4*)(gW + (size_t)(c + 1) * 32 * Nt + 4 * j));
                uint2 h, l;
                cvt_hilo(vb, h, l);
                int off = bk * PADN + bn + 4 * j;
                *(uint2*)(st + O_BH + off * 2) = h;
                *(uint2*)(st + O_BL + off * 2) = l;
            }
        }
        __syncthreads();
    }

    // epilogue: bias + relu
    int erow = row0 + wm + (lane >> 2);
    int ecol0 = col0 + wn + (lane & 3) * 2;
#pragma unroll
    for (int nt = 0; nt < 4; nt++) {
        int cc = ecol0 + nt * 8;
        float bx = __ldg(bias + cc), by = __ldg(bias + cc + 1);
#pragma unroll
        for (int mt = 0; mt < 2; mt++) {
            int r = erow + mt * 16;
            if (r < M) {
                float2 o;
                o.x = fmaxf(acc[mt][nt][0] + bx, 0.f);
                o.y = fmaxf(acc[mt][nt][1] + by, 0.f);
                *(float2*)(C + (size_t)r * Nt + cc) = o;
            }
            if (r + 8 < M) {
                float2 o;
                o.x = fmaxf(acc[mt][nt][2] + bx, 0.f);
                o.y = fmaxf(acc[mt][nt][3] + by, 0.f);
                *(float2*)(C + (size_t)(r + 8) * Nt + cc) = o;
            }
        }
    }
}

// ---------------- launch ----------------------------------------------------

extern "C" void kernel_launch(void* const* d_in, const int* in_sizes, int n_in,
                              void* d_out, int out_size) {
    const float* x    = (const float*)d_in[0];
    const int*   src0 = (const int*)d_in[1];
    const int*   dst0 = (const int*)d_in[2];
    const int*   src1 = (const int*)d_in[3];
    const int*   dst1 = (const int*)d_in[4];
    const float* W1   = (const float*)d_in[5];
    const float* b1   = (const float*)d_in[6];
    const float* W2   = (const float*)d_in[7];
    const float* b2   = (const float*)d_in[8];
    float* out = (float*)d_out;

    float *agg0, *h1, *agg1, *nrm;
    int *ints, *rpc, *col0, *col1, *part;
    cudaGetSymbolAddress((void**)&agg0, g_agg0);
    cudaGetSymbolAddress((void**)&h1,   g_h1);
    cudaGetSymbolAddress((void**)&agg1, g_agg1);
    cudaGetSymbolAddress((void**)&nrm,  g_norm);
    cudaGetSymbolAddress((void**)&ints, g_ints);
    cudaGetSymbolAddress((void**)&rpc,  g_rpc);
    cudaGetSymbolAddress((void**)&col0, g_col0);
    cudaGetSymbolAddress((void**)&col1, g_col1);
    cudaGetSymbolAddress((void**)&part, g_part);

    cudaFuncSetAttribute(k_gemm_f, cudaFuncAttributeMaxDynamicSharedMemorySize, GSM_TOTAL);

    const float* outn0 = nrm + OFF_C_SRC0;
    const float* din1  = nrm + OFF_C_DST1;
    const float* din0  = nrm + OFF_C_DST0;
    const float* outn1 = nrm + OFF_C_SRC1;

    // 1) zero agg0 + counters/cursors
    k_zero2<<<2048, 256>>>((float4*)agg0, (int)((size_t)N_DST0 * IN_F / 4), ints, N_INTS);

    // 2) degree counts
    k_count<<<(E0V + E1V + 255) / 256, 256>>>(src0, dst0, src1, dst1, ints);

    // 3) combined scan over [src0 counts | dst1 counts] (104000)
    {
        int nb = (N_SCAN + 1023) / 1024;   // 102
        k_scan1<<<nb, 1024>>>(ints, rpc, part, N_SCAN);
        k_scan2<<<1, 128>>>(part, nb, rpc);
        k_scan3<<<nb, 1024>>>(rpc, part, N_SCAN);
    }

    // 4) fused norms + both CSR fills
    k_fill_norm<<<(E0V + E1V + 255) / 256, 256>>>(src0, dst0, src1, dst1,
                                                  rpc, ints, col0, col1, nrm);

    // 5) layer-1 scatter into L2-resident agg0
    k_scatter_src<<<(N_SRC0 * 32 + 255) / 256, 256>>>(x, rpc, col0, outn0, agg0, N_SRC0);

    // 6) fused GEMM1: h1 = relu((agg0*din0) @ W1 + b1)
    {
        dim3 grid(HID_F / 128, (N_DST0 + 63) / 64);   // (4, 313)
        k_gemm_f<<<grid, 256, GSM_TOTAL>>>(agg0, din0, W1, b1, h1, N_DST0, HID_F);
    }

    // 7) layer-2 gather (h1 in L2)
    k_gather_dst<<<(N_DST1 * 32 + 255) / 256, 256>>>(h1, rpc + OFF_C_DST1, col1,
                                                     outn1, agg1, N_DST1);

    // 8) fused GEMM2: out = relu((agg1*din1) @ W2 + b2)
    {
        dim3 grid(OUT_F / 128, (N_DST1 + 63) / 64);   // (2, 63)
        k_gemm_f<<<grid, 256, GSM_TOTAL>>>(agg1, din1, W2, b2, out, N_DST1, OUT_F);
    }
}

// round 10
// speedup vs baseline: 1.1767x; 1.1767x over previous
#include <cuda_runtime.h>
#include <cuda_bf16.h>
#include <cuda_fp16.h>
#include <cstdint>

#define N_SRC0 100000
#define N_DST0 20000
#define N_DST1 4000
#define E0V 640000
#define E1V 128000
#define IN_F 512
#define HID_F 512
#define OUT_F 256

// ---------------- scratch (device globals) ----------------------------------
__device__ float g_agg0[(size_t)N_DST0 * IN_F];
__device__ float g_h1[(size_t)N_DST0 * HID_F];
__device__ float g_agg1[(size_t)N_DST1 * HID_F];

// count layout: [C_SRC0 (100000) | C_DST1 (4000) | C_DST0 (20000) | C_SRC1 (20000)]
#define OFF_C_SRC0 0
#define OFF_C_DST1 100000
#define OFF_C_DST0 104000
#define OFF_C_SRC1 124000
#define N_CNT      144000
#define OFF_CUR0   144000
#define OFF_CUR1   244000
#define N_INTS     248000
#define N_SCAN     104000
__device__ int g_ints[N_INTS];
__device__ float g_norm[N_CNT];

__device__ int g_rpc[N_SCAN + 1];
__device__ int g_col0[E0V];
__device__ int g_col1[E1V];
__device__ int g_part[256];

// ---------------- utility kernels -------------------------------------------

__global__ void k_zero2(float4* __restrict__ a, int n4, int* __restrict__ b, int nb) {
    int stride = gridDim.x * blockDim.x;
    for (int i = blockIdx.x * blockDim.x + threadIdx.x; i < n4; i += stride)
        a[i] = make_float4(0.f, 0.f, 0.f, 0.f);
    for (int i = blockIdx.x * blockDim.x + threadIdx.x; i < nb; i += stride)
        b[i] = 0;
}

__global__ void k_count(const int* __restrict__ s0, const int* __restrict__ d0,
                        const int* __restrict__ s1, const int* __restrict__ d1,
                        int* __restrict__ ints) {
    int i = blockIdx.x * blockDim.x + threadIdx.x;
    if (i < E0V) {
        atomicAdd(ints + OFF_C_SRC0 + s0[i], 1);
        atomicAdd(ints + OFF_C_DST0 + d0[i], 1);
    } else {
        int j = i - E0V;
        if (j < E1V) {
            atomicAdd(ints + OFF_C_SRC1 + s1[j], 1);
            atomicAdd(ints + OFF_C_DST1 + d1[j], 1);
        }
    }
}

// warp-shuffle block scan (1024 threads)
__global__ void k_scan1(const int* __restrict__ cnt, int* __restrict__ rp,
                        int* __restrict__ part, int n) {
    __shared__ int ws[32];
    int tid = threadIdx.x;
    int lane = tid & 31, warp = tid >> 5;
    int i = blockIdx.x * 1024 + tid;
    int s = (i < n) ? cnt[i] : 0;
#pragma unroll
    for (int d = 1; d < 32; d <<= 1) {
        int t = __shfl_up_sync(0xffffffffu, s, d);
        if (lane >= d) s += t;
    }
    if (lane == 31) ws[warp] = s;
    __syncthreads();
    if (warp == 0) {
        int w = ws[lane];
#pragma unroll
        for (int d = 1; d < 32; d <<= 1) {
            int t = __shfl_up_sync(0xffffffffu, w, d);
            if (lane >= d) w += t;
        }
        ws[lane] = w;
    }
    __syncthreads();
    if (warp > 0) s += ws[warp - 1];
    if (i < n) rp[i + 1] = s;
    if (tid == 1023) part[blockIdx.x] = s;
}

__global__ void k_scan2(int* __restrict__ part, int nb, int* __restrict__ rp) {
    __shared__ int sd[128];
    int tid = threadIdx.x;
    sd[tid] = (tid < nb) ? part[tid] : 0;
    __syncthreads();
#pragma unroll
    for (int d = 1; d < 128; d <<= 1) {
        int t = (tid >= d) ? sd[tid - d] : 0;
        __syncthreads();
        sd[tid] += t;
        __syncthreads();
    }
    if (tid < nb) part[tid] = (tid == 0) ? 0 : sd[tid - 1];
    if (tid == 0) rp[0] = 0;
}

__global__ void k_scan3(int* __restrict__ rp, const int* __restrict__ part, int n) {
    int b = blockIdx.x;
    if (b == 0) return;
    int i = b * 1024 + threadIdx.x;
    if (i < n) rp[i + 1] += part[b];
}

// fused: norms + both CSR fills
__global__ void k_fill_norm(const int* __restrict__ src0, const int* __restrict__ dst0,
                            const int* __restrict__ src1, const int* __restrict__ dst1,
                            const int* __restrict__ rpc, int* __restrict__ ints,
                            int* __restrict__ col0, int* __restrict__ col1,
                            float* __restrict__ nrm) {
    int i = blockIdx.x * blockDim.x + threadIdx.x;
    if (i < N_CNT) nrm[i] = rsqrtf(fmaxf((float)ints[i], 1.0f));
    if (i < E0V) {
        int k = src0[i];
        int pos = rpc[k] + atomicAdd(ints + OFF_CUR0 + k, 1);
        col0[pos] = dst0[i];
    } else {
        int j = i - E0V;
        if (j < E1V) {
            int k = dst1[j];
            int pos = rpc[OFF_C_DST1 + k] - E0V + atomicAdd(ints + OFF_CUR1 + k, 1);
            col1[pos] = src1[j];
        }
    }
}

// ---------------- layer-1: CSR-by-src scatter --------------------------------
__global__ void k_scatter_src(const float* __restrict__ x,
                              const int* __restrict__ rp, const int* __restrict__ col,
                              const float* __restrict__ outn,
                              float* __restrict__ agg, int n_src) {
    int w = (blockIdx.x * blockDim.x + threadIdx.x) >> 5;
    int lane = threadIdx.x & 31;
    if (w >= n_src) return;
    int beg = rp[w], end = rp[w + 1];
    if (beg == end) return;
    float sc = outn[w];
    const float4* xp = reinterpret_cast<const float4*>(x) + (size_t)w * (IN_F / 4) + lane;
    float4 v0 = xp[0], v1 = xp[32], v2 = xp[64], v3 = xp[96];
    v0.x *= sc; v0.y *= sc; v0.z *= sc; v0.w *= sc;
    v1.x *= sc; v1.y *= sc; v1.z *= sc; v1.w *= sc;
    v2.x *= sc; v2.y *= sc; v2.z *= sc; v2.w *= sc;
    v3.x *= sc; v3.y *= sc; v3.z *= sc; v3.w *= sc;
    for (int e = beg; e < end; e++) {
        int d = __ldg(col + e);
        float* ap = agg + (size_t)d * IN_F + lane * 4;
        asm volatile("red.global.add.v4.f32 [%0], {%1, %2, %3, %4};"
                     :: "l"(ap), "f"(v0.x), "f"(v0.y), "f"(v0.z), "f"(v0.w) : "memory");
        asm volatile("red.global.add.v4.f32 [%0], {%1, %2, %3, %4};"
                     :: "l"(ap + 128), "f"(v1.x), "f"(v1.y), "f"(v1.z), "f"(v1.w) : "memory");
        asm volatile("red.global.add.v4.f32 [%0], {%1, %2, %3, %4};"
                     :: "l"(ap + 256), "f"(v2.x), "f"(v2.y), "f"(v2.z), "f"(v2.w) : "memory");
        asm volatile("red.global.add.v4.f32 [%0], {%1, %2, %3, %4};"
                     :: "l"(ap + 384), "f"(v3.x), "f"(v3.y), "f"(v3.z), "f"(v3.w) : "memory");
    }
}

// ---------------- layer-2: CSR-by-dst gather ---------------------------------
__global__ void k_gather_dst(const float* __restrict__ h,
                             const int* __restrict__ rp1, const int* __restrict__ col,
                             const float* __restrict__ outn,
                             float* __restrict__ agg, int n_dst) {
    int w = (blockIdx.x * blockDim.x + threadIdx.x) >> 5;
    int lane = threadIdx.x & 31;
    if (w >= n_dst) return;
    int beg = rp1[w] - E0V, end = rp1[w + 1] - E0V;
    float4 a0 = make_float4(0.f, 0.f, 0.f, 0.f);
    float4 a1 = a0, a2 = a0, a3 = a0;
    for (int e = beg; e < end; e++) {
        int s = __ldg(col + e);
        float sc = __ldg(outn + s);
        const float4* hp = reinterpret_cast<const float4*>(h) + (size_t)s * (HID_F / 4) + lane;
        float4 v0 = __ldg(hp), v1 = __ldg(hp + 32), v2 = __ldg(hp + 64), v3 = __ldg(hp + 96);
        a0.x = fmaf(v0.x, sc, a0.x); a0.y = fmaf(v0.y, sc, a0.y);
        a0.z = fmaf(v0.z, sc, a0.z); a0.w = fmaf(v0.w, sc, a0.w);
        a1.x = fmaf(v1.x, sc, a1.x); a1.y = fmaf(v1.y, sc, a1.y);
        a1.z = fmaf(v1.z, sc, a1.z); a1.w = fmaf(v1.w, sc, a1.w);
        a2.x = fmaf(v2.x, sc, a2.x); a2.y = fmaf(v2.y, sc, a2.y);
        a2.z = fmaf(v2.z, sc, a2.z); a2.w = fmaf(v2.w, sc, a2.w);
        a3.x = fmaf(v3.x, sc, a3.x); a3.y = fmaf(v3.y, sc, a3.y);
        a3.z = fmaf(v3.z, sc, a3.z); a3.w = fmaf(v3.w, sc, a3.w);
    }
    float4* ap = reinterpret_cast<float4*>(agg) + (size_t)w * (HID_F / 4) + lane;
    ap[0] = a0; ap[32] = a1; ap[64] = a2; ap[96] = a3;
}

// ---------------- fused fp32->fp16 single-product HMMA GEMM ------------------
// C[64,128] = relu( (A[M,512]*rs) @ W[512,Nt] + bias ). fp16 operands, fp32 acc.
// 256 thr = 8 warps (2x4), warp tile 32x32; double-buffered; 2 CTAs/SM.
#define PADK 40
#define PADN 136
#define SZ_A (64 * PADK * 2)               // 5120
#define SZ_B (32 * PADN * 2)               // 8704
#define STAGE_BYTES (SZ_A + SZ_B)          // 13824
#define GSM_TOTAL (2 * STAGE_BYTES)        // 27648
#define O_AH 0
#define O_BH SZ_A

__device__ __forceinline__ void ldm4(uint32_t* f, uint32_t addr) {
    asm volatile("ldmatrix.sync.aligned.m8n8.x4.shared.b16 {%0,%1,%2,%3}, [%4];"
                 : "=r"(f[0]), "=r"(f[1]), "=r"(f[2]), "=r"(f[3]) : "r"(addr));
}
__device__ __forceinline__ void ldm4t(uint32_t* f, uint32_t addr) {
    asm volatile("ldmatrix.sync.aligned.m8n8.x4.trans.shared.b16 {%0,%1,%2,%3}, [%4];"
                 : "=r"(f[0]), "=r"(f[1]), "=r"(f[2]), "=r"(f[3]) : "r"(addr));
}
__device__ __forceinline__ void mma16816h(float* c, const uint32_t* a, const uint32_t* b) {
    asm volatile("mma.sync.aligned.m16n8k16.row.col.f32.f16.f16.f32 "
                 "{%0,%1,%2,%3}, {%4,%5,%6,%7}, {%8,%9}, {%0,%1,%2,%3};"
                 : "+f"(c[0]), "+f"(c[1]), "+f"(c[2]), "+f"(c[3])
                 : "r"(a[0]), "r"(a[1]), "r"(a[2]), "r"(a[3]), "r"(b[0]), "r"(b[1]));
}
__device__ __forceinline__ uint2 cvt_h(float4 v) {
    __half2 h0 = __floats2half2_rn(v.x, v.y);
    __half2 h1 = __floats2half2_rn(v.z, v.w);
    uint2 r;
    r.x = *reinterpret_cast<uint32_t*>(&h0);
    r.y = *reinterpret_cast<uint32_t*>(&h1);
    return r;
}

__global__ __launch_bounds__(256, 2) void k_gemm_f(
    const float* __restrict__ A, const float* __restrict__ rs,
    const float* __restrict__ W, const float* __restrict__ bias,
    float* __restrict__ C, int M, int Nt) {
    extern __shared__ char smem[];
    int tid = threadIdx.x;
    int wid = tid >> 5, lane = tid & 31;
    int wm = (wid >> 2) * 32;
    int wn = (wid & 3) * 32;
    int row0 = blockIdx.y * 64, col0 = blockIdx.x * 128;

    // A staging: row sr (0..63), 8-col group; 2 float4 per thread
    int sr = tid >> 2;
    int sk = (tid & 3) * 8;
    int rowA = row0 + sr;
    bool aval = rowA < M;
    float scA = aval ? __ldg(rs + rowA) : 0.f;
    const float* gA = A + (size_t)(aval ? rowA : 0) * 512 + sk;
    // B staging: k row bk (0..31), 16-wide n group; 4 float4 per thread
    int bk = tid >> 3;
    int bn = (tid & 7) * 16;
    const float* gW = W + (size_t)bk * Nt + col0 + bn;

    uint32_t ubase = (uint32_t)__cvta_generic_to_shared(smem);

    int aRow = wm + (lane & 15);
    int aCol = (lane >> 4) << 3;
    int kIdx = (lane & 7) + (((lane >> 3) & 1) << 3);
    int nOff = (lane >> 4) << 3;

    float acc[2][4][4];
#pragma unroll
    for (int i = 0; i < 2; i++)
#pragma unroll
        for (int j = 0; j < 4; j++)
#pragma unroll
            for (int k = 0; k < 4; k++) acc[i][j][k] = 0.f;

    // stage chunk 0 -> buffer 0
    {
        char* st = smem;
#pragma unroll
        for (int j = 0; j < 2; j++) {
            float4 va = aval ? __ldg((const float4*)(gA + 4 * j)) : make_float4(0, 0, 0, 0);
            va.x *= scA; va.y *= scA; va.z *= scA; va.w *= scA;
            *(uint2*)(st + O_AH + (sr * PADK + sk + 4 * j) * 2) = cvt_h(va);
        }
#pragma unroll
        for (int j = 0; j < 4; j++) {
            float4 vb = __ldg((const float4*)(gW + 4 * j));
            *(uint2*)(st + O_BH + (bk * PADN + bn + 4 * j) * 2) = cvt_h(vb);
        }
    }
    __syncthreads();

    for (int c = 0; c < 16; c++) {
        uint32_t ub = ubase + (c & 1) * STAGE_BYTES;

        // prefetch next chunk into registers (hidden by MMAs below)
        float4 pa[2], pb[4];
        if (c < 15) {
            int ka = (c + 1) * 32;
#pragma unroll
            for (int j = 0; j < 2; j++)
                pa[j] = aval ? __ldg((const float4*)(gA + ka + 4 * j))
                             : make_float4(0, 0, 0, 0);
#pragma unroll
            for (int j = 0; j < 4; j++)
                pb[j] = __ldg((const float4*)(gW + (size_t)(c + 1) * 32 * Nt + 4 * j));
        }

#pragma unroll
        for (int ks = 0; ks < 32; ks += 16) {
            uint32_t ah[2][4], bh[4][2];
#pragma unroll
            for (int mt = 0; mt < 2; mt++) {
                uint32_t off = ((uint32_t)((aRow + mt * 16) * PADK + ks + aCol)) * 2;
                ldm4(ah[mt], ub + O_AH + off);
            }
#pragma unroll
            for (int ntp = 0; ntp < 2; ntp++) {
                uint32_t off = ((uint32_t)((ks + kIdx) * PADN + wn + ntp * 16 + nOff)) * 2;
                uint32_t t[4];
                ldm4t(t, ub + O_BH + off);
                bh[ntp * 2][0] = t[0]; bh[ntp * 2][1] = t[1];
                bh[ntp * 2 + 1][0] = t[2]; bh[ntp * 2 + 1][1] = t[3];
            }
#pragma unroll
            for (int mt = 0; mt < 2; mt++)
#pragma unroll
                for (int nt = 0; nt < 4; nt++)
                    mma16816h(acc[mt][nt], ah[mt], bh[nt]);
        }

        if (c < 15) {
            char* st = smem + ((c & 1) ^ 1) * STAGE_BYTES;
#pragma unroll
            for (int j = 0; j < 2; j++) {
                float4 va = pa[j];
                va.x *= scA; va.y *= scA; va.z *= scA; va.w *= scA;
                *(uint2*)(st + O_AH + (sr * PADK + sk + 4 * j) * 2) = cvt_h(va);
            }
#pragma unroll
            for (int j = 0; j < 4; j++)
                *(uint2*)(st + O_BH + (bk * PADN + bn + 4 * j) * 2) = cvt_h(pb[j]);
        }
        __syncthreads();
    }

    // epilogue: bias + relu
    int erow = row0 + wm + (lane >> 2);
    int ecol0 = col0 + wn + (lane & 3) * 2;
#pragma unroll
    for (int nt = 0; nt < 4; nt++) {
        int cc = ecol0 + nt * 8;
        float bx = __ldg(bias + cc), by = __ldg(bias + cc + 1);
#pragma unroll
        for (int mt = 0; mt < 2; mt++) {
            int r = erow + mt * 16;
            if (r < M) {
                float2 o;
                o.x = fmaxf(acc[mt][nt][0] + bx, 0.f);
                o.y = fmaxf(acc[mt][nt][1] + by, 0.f);
                *(float2*)(C + (size_t)r * Nt + cc) = o;
            }
            if (r + 8 < M) {
                float2 o;
                o.x = fmaxf(acc[mt][nt][2] + bx, 0.f);
                o.y = fmaxf(acc[mt][nt][3] + by, 0.f);
                *(float2*)(C + (size_t)(r + 8) * Nt + cc) = o;
            }
        }
    }
}

// ---------------- launch ----------------------------------------------------

extern "C" void kernel_launch(void* const* d_in, const int* in_sizes, int n_in,
                              void* d_out, int out_size) {
    const float* x    = (const float*)d_in[0];
    const int*   src0 = (const int*)d_in[1];
    const int*   dst0 = (const int*)d_in[2];
    const int*   src1 = (const int*)d_in[3];
    const int*   dst1 = (const int*)d_in[4];
    const float* W1   = (const float*)d_in[5];
    const float* b1   = (const float*)d_in[6];
    const float* W2   = (const float*)d_in[7];
    const float* b2   = (const float*)d_in[8];
    float* out = (float*)d_out;

    float *agg0, *h1, *agg1, *nrm;
    int *ints, *rpc, *col0, *col1, *part;
    cudaGetSymbolAddress((void**)&agg0, g_agg0);
    cudaGetSymbolAddress((void**)&h1,   g_h1);
    cudaGetSymbolAddress((void**)&agg1, g_agg1);
    cudaGetSymbolAddress((void**)&nrm,  g_norm);
    cudaGetSymbolAddress((void**)&ints, g_ints);
    cudaGetSymbolAddress((void**)&rpc,  g_rpc);
    cudaGetSymbolAddress((void**)&col0, g_col0);
    cudaGetSymbolAddress((void**)&col1, g_col1);
    cudaGetSymbolAddress((void**)&part, g_part);

    cudaFuncSetAttribute(k_gemm_f, cudaFuncAttributeMaxDynamicSharedMemorySize, GSM_TOTAL);

    const float* outn0 = nrm + OFF_C_SRC0;
    const float* din1  = nrm + OFF_C_DST1;
    const float* din0  = nrm + OFF_C_DST0;
    const float* outn1 = nrm + OFF_C_SRC1;

    // 1) zero agg0 + counters/cursors
    k_zero2<<<2048, 256>>>((float4*)agg0, (int)((size_t)N_DST0 * IN_F / 4), ints, N_INTS);

    // 2) degree counts
    k_count<<<(E0V + E1V + 255) / 256, 256>>>(src0, dst0, src1, dst1, ints);

    // 3) combined scan over [src0 counts | dst1 counts]
    {
        int nb = (N_SCAN + 1023) / 1024;
        k_scan1<<<nb, 1024>>>(ints, rpc, part, N_SCAN);
        k_scan2<<<1, 128>>>(part, nb, rpc);
        k_scan3<<<nb, 1024>>>(rpc, part, N_SCAN);
    }

    // 4) fused norms + both CSR fills
    k_fill_norm<<<(E0V + E1V + 255) / 256, 256>>>(src0, dst0, src1, dst1,
                                                  rpc, ints, col0, col1, nrm);

    // 5) layer-1 scatter into L2-resident agg0
    k_scatter_src<<<(N_SRC0 * 32 + 255) / 256, 256>>>(x, rpc, col0, outn0, agg0, N_SRC0);

    // 6) fused GEMM1: h1 = relu((agg0*din0) @ W1 + b1)
    {
        dim3 grid(HID_F / 128, (N_DST0 + 63) / 64);   // (4, 313)
        k_gemm_f<<<grid, 256, GSM_TOTAL>>>(agg0, din0, W1, b1, h1, N_DST0, HID_F);
    }

    // 7) layer-2 gather (h1 in L2)
    k_gather_dst<<<(N_DST1 * 32 + 255) / 256, 256>>>(h1, rpc + OFF_C_DST1, col1,
                                                     outn1, agg1, N_DST1);

    // 8) fused GEMM2: out = relu((agg1*din1) @ W2 + b2)
    {
        dim3 grid(OUT_F / 128, (N_DST1 + 63) / 64);   // (2, 63)
        k_gemm_f<<<grid, 256, GSM_TOTAL>>>(agg1, din1, W2, b2, out, N_DST1, OUT_F);
    }
}

// round 11
// speedup vs baseline: 1.6402x; 1.3939x over previous
#include <cuda_runtime.h>
#include <cuda_fp16.h>
#include <cstdint>

#define N_SRC0 100000
#define N_DST0 20000
#define N_DST1 4000
#define E0V 640000
#define E1V 128000
#define IN_F 512
#define HID_F 512
#define OUT_F 256

// ---------------- scratch (device globals) ----------------------------------
__device__ __half g_agg0h[(size_t)N_DST0 * IN_F];    // din0-scaled aggregate, fp16
__device__ __half g_h1h[(size_t)N_DST0 * HID_F];     // relu output layer1, fp16
__device__ __half g_agg1h[(size_t)N_DST1 * HID_F];   // din1-scaled aggregate, fp16
__device__ __half g_w1h[512 * 512];
__device__ __half g_w2h[512 * 256];

// count layout: [C_DST0 (20000) | C_DST1 (4000) | C_SRC0 (100000) | C_SRC1 (20000)]
// scan covers the first 24000 (dst0|dst1).
#define OFF_C_DST0 0
#define OFF_C_DST1 20000
#define OFF_C_SRC0 24000
#define OFF_C_SRC1 124000
#define N_CNT      144000
#define OFF_CUR0   144000
#define OFF_CUR1   164000
#define N_INTS     168000
#define N_SCAN     24000
__device__ int g_ints[N_INTS];
__device__ float g_norm[N_CNT];

__device__ int g_rpc[N_SCAN + 1];
__device__ int g_col0[E0V];   // src indices, sorted by dst0
__device__ int g_col1[E1V];   // src indices, sorted by dst1
__device__ int g_part[256];

// ---------------- utility kernels -------------------------------------------

__global__ void k_zeroi(int* __restrict__ b, int nb) {
    int stride = gridDim.x * blockDim.x;
    for (int i = blockIdx.x * blockDim.x + threadIdx.x; i < nb; i += stride)
        b[i] = 0;
}

__global__ void k_count(const int* __restrict__ s0, const int* __restrict__ d0,
                        const int* __restrict__ s1, const int* __restrict__ d1,
                        int* __restrict__ ints) {
    int i = blockIdx.x * blockDim.x + threadIdx.x;
    if (i < E0V) {
        atomicAdd(ints + OFF_C_SRC0 + s0[i], 1);
        atomicAdd(ints + OFF_C_DST0 + d0[i], 1);
    } else {
        int j = i - E0V;
        if (j < E1V) {
            atomicAdd(ints + OFF_C_SRC1 + s1[j], 1);
            atomicAdd(ints + OFF_C_DST1 + d1[j], 1);
        }
    }
}

// warp-shuffle block scan (1024 threads)
__global__ void k_scan1(const int* __restrict__ cnt, int* __restrict__ rp,
                        int* __restrict__ part, int n) {
    __shared__ int ws[32];
    int tid = threadIdx.x;
    int lane = tid & 31, warp = tid >> 5;
    int i = blockIdx.x * 1024 + tid;
    int s = (i < n) ? cnt[i] : 0;
#pragma unroll
    for (int d = 1; d < 32; d <<= 1) {
        int t = __shfl_up_sync(0xffffffffu, s, d);
        if (lane >= d) s += t;
    }
    if (lane == 31) ws[warp] = s;
    __syncthreads();
    if (warp == 0) {
        int w = ws[lane];
#pragma unroll
        for (int d = 1; d < 32; d <<= 1) {
            int t = __shfl_up_sync(0xffffffffu, w, d);
            if (lane >= d) w += t;
        }
        ws[lane] = w;
    }
    __syncthreads();
    if (warp > 0) s += ws[warp - 1];
    if (i < n) rp[i + 1] = s;
    if (tid == 1023) part[blockIdx.x] = s;
}

__global__ void k_scan2(int* __restrict__ part, int nb, int* __restrict__ rp) {
    __shared__ int sd[128];
    int tid = threadIdx.x;
    sd[tid] = (tid < nb) ? part[tid] : 0;
    __syncthreads();
#pragma unroll
    for (int d = 1; d < 128; d <<= 1) {
        int t = (tid >= d) ? sd[tid - d] : 0;
        __syncthreads();
        sd[tid] += t;
        __syncthreads();
    }
    if (tid < nb) part[tid] = (tid == 0) ? 0 : sd[tid - 1];
    if (tid == 0) rp[0] = 0;
}

__global__ void k_scan3(int* __restrict__ rp, const int* __restrict__ part, int n) {
    int b = blockIdx.x;
    if (b == 0) return;
    int i = b * 1024 + threadIdx.x;
    if (i < n) rp[i + 1] += part[b];
}

// fused: norms + both CSC fills (edges sorted by dst)
__global__ void k_fill_norm(const int* __restrict__ src0, const int* __restrict__ dst0,
                            const int* __restrict__ src1, const int* __restrict__ dst1,
                            const int* __restrict__ rpc, int* __restrict__ ints,
                            int* __restrict__ col0, int* __restrict__ col1,
                            float* __restrict__ nrm) {
    int i = blockIdx.x * blockDim.x + threadIdx.x;
    if (i < N_CNT) nrm[i] = rsqrtf(fmaxf((float)ints[i], 1.0f));
    if (i < E0V) {
        int k = dst0[i];
        int pos = rpc[k] + atomicAdd(ints + OFF_CUR0 + k, 1);
        col0[pos] = src0[i];
    } else {
        int j = i - E0V;
        if (j < E1V) {
            int k = dst1[j];
            int pos = rpc[OFF_C_DST1 + k] - E0V + atomicAdd(ints + OFF_CUR1 + k, 1);
            col1[pos] = src1[j];
        }
    }
}

// W fp32 -> fp16 (flat copy, both layers)
__global__ void k_wprep(const float* __restrict__ W1, const float* __restrict__ W2,
                        __half* __restrict__ w1h, __half* __restrict__ w2h) {
    int i = blockIdx.x * blockDim.x + threadIdx.x;   // float2 granularity
    if (i < 512 * 256) {
        float2 v = reinterpret_cast<const float2*>(W1)[i];
        reinterpret_cast<__half2*>(w1h)[i] = __floats2half2_rn(v.x, v.y);
    } else {
        int j = i - 512 * 256;
        if (j < 256 * 256) {
            float2 v = reinterpret_cast<const float2*>(W2)[j];
            reinterpret_cast<__half2*>(w2h)[j] = __floats2half2_rn(v.x, v.y);
        }
    }
}

// ---------------- layer-1: CSC-by-dst gather (fp32 acc, fp16 out) -----------
__global__ void k_gather0(const float* __restrict__ x,
                          const int* __restrict__ rp, const int* __restrict__ col,
                          const float* __restrict__ outn, const float* __restrict__ din,
                          __half* __restrict__ aggh, int n_dst) {
    int w = (blockIdx.x * blockDim.x + threadIdx.x) >> 5;
    int lane = threadIdx.x & 31;
    if (w >= n_dst) return;
    int beg = rp[w], end = rp[w + 1];
    float4 a0 = make_float4(0.f, 0.f, 0.f, 0.f);
    float4 a1 = a0, a2 = a0, a3 = a0;
    for (int e = beg; e < end; e++) {
        int s = __ldg(col + e);
        float sc = __ldg(outn + s);
        const float4* xp = reinterpret_cast<const float4*>(x) + (size_t)s * (IN_F / 4) + lane;
        float4 v0 = __ldg(xp), v1 = __ldg(xp + 32), v2 = __ldg(xp + 64), v3 = __ldg(xp + 96);
        a0.x = fmaf(v0.x, sc, a0.x); a0.y = fmaf(v0.y, sc, a0.y);
        a0.z = fmaf(v0.z, sc, a0.z); a0.w = fmaf(v0.w, sc, a0.w);
        a1.x = fmaf(v1.x, sc, a1.x); a1.y = fmaf(v1.y, sc, a1.y);
        a1.z = fmaf(v1.z, sc, a1.z); a1.w = fmaf(v1.w, sc, a1.w);
        a2.x = fmaf(v2.x, sc, a2.x); a2.y = fmaf(v2.y, sc, a2.y);
        a2.z = fmaf(v2.z, sc, a2.z); a2.w = fmaf(v2.w, sc, a2.w);
        a3.x = fmaf(v3.x, sc, a3.x); a3.y = fmaf(v3.y, sc, a3.y);
        a3.z = fmaf(v3.z, sc, a3.z); a3.w = fmaf(v3.w, sc, a3.w);
    }
    float d = din[w];
    uint2* op = reinterpret_cast<uint2*>(aggh + (size_t)w * IN_F) + lane;
    __half2 h0, h1;
    h0 = __floats2half2_rn(a0.x * d, a0.y * d); h1 = __floats2half2_rn(a0.z * d, a0.w * d);
    op[0] = make_uint2(*(uint32_t*)&h0, *(uint32_t*)&h1);
    h0 = __floats2half2_rn(a1.x * d, a1.y * d); h1 = __floats2half2_rn(a1.z * d, a1.w * d);
    op[32] = make_uint2(*(uint32_t*)&h0, *(uint32_t*)&h1);
    h0 = __floats2half2_rn(a2.x * d, a2.y * d); h1 = __floats2half2_rn(a2.z * d, a2.w * d);
    op[64] = make_uint2(*(uint32_t*)&h0, *(uint32_t*)&h1);
    h0 = __floats2half2_rn(a3.x * d, a3.y * d); h1 = __floats2half2_rn(a3.z * d, a3.w * d);
    op[96] = make_uint2(*(uint32_t*)&h0, *(uint32_t*)&h1);
}

// ---------------- layer-2: CSC-by-dst gather over fp16 h1 -------------------
__global__ void k_gather1(const __half* __restrict__ h,
                          const int* __restrict__ rp1, const int* __restrict__ col,
                          const float* __restrict__ outn, const float* __restrict__ din,
                          __half* __restrict__ aggh, int n_dst) {
    int w = (blockIdx.x * blockDim.x + threadIdx.x) >> 5;
    int lane = threadIdx.x & 31;
    if (w >= n_dst) return;
    int beg = rp1[w] - E0V, end = rp1[w + 1] - E0V;
    float acc[16];
#pragma unroll
    for (int i = 0; i < 16; i++) acc[i] = 0.f;
    for (int e = beg; e < end; e++) {
        int s = __ldg(col + e);
        float sc = __ldg(outn + s);
        const uint4* hp = reinterpret_cast<const uint4*>(h + (size_t)s * HID_F) + 2 * lane;
        uint4 p = __ldg(hp), q = __ldg(hp + 1);
        const uint32_t pr[8] = {p.x, p.y, p.z, p.w, q.x, q.y, q.z, q.w};
#pragma unroll
        for (int i = 0; i < 8; i++) {
            float2 f = __half22float2(*(const __half2*)&pr[i]);
            acc[2 * i]     = fmaf(f.x, sc, acc[2 * i]);
            acc[2 * i + 1] = fmaf(f.y, sc, acc[2 * i + 1]);
        }
    }
    float d = din[w];
    uint32_t o[8];
#pragma unroll
    for (int i = 0; i < 8; i++) {
        __half2 h2 = __floats2half2_rn(acc[2 * i] * d, acc[2 * i + 1] * d);
        o[i] = *(uint32_t*)&h2;
    }
    uint4* op = reinterpret_cast<uint4*>(aggh + (size_t)w * HID_F) + 2 * lane;
    op[0] = make_uint4(o[0], o[1], o[2], o[3]);
    op[1] = make_uint4(o[4], o[5], o[6], o[7]);
}

// ---------------- fp16 HMMA GEMM: C = relu(A @ B + bias) ---------------------
// A [M,512] fp16 row-major, B [512,Nt] fp16 row-major. 64x128 CTA tile,
// 8 warps (2x4), warp tile 32x32, double-buffered, 2 CTAs/SM.
#define PADK 40
#define PADN 136
#define SZ_A (64 * PADK * 2)               // 5120
#define SZ_B (32 * PADN * 2)               // 8704
#define STAGE_BYTES (SZ_A + SZ_B)          // 13824
#define GSM_TOTAL (2 * STAGE_BYTES)        // 27648
#define O_AH 0
#define O_BH SZ_A

__device__ __forceinline__ void ldm4(uint32_t* f, uint32_t addr) {
    asm volatile("ldmatrix.sync.aligned.m8n8.x4.shared.b16 {%0,%1,%2,%3}, [%4];"
                 : "=r"(f[0]), "=r"(f[1]), "=r"(f[2]), "=r"(f[3]) : "r"(addr));
}
__device__ __forceinline__ void ldm4t(uint32_t* f, uint32_t addr) {
    asm volatile("ldmatrix.sync.aligned.m8n8.x4.trans.shared.b16 {%0,%1,%2,%3}, [%4];"
                 : "=r"(f[0]), "=r"(f[1]), "=r"(f[2]), "=r"(f[3]) : "r"(addr));
}
__device__ __forceinline__ void mma16816h(float* c, const uint32_t* a, const uint32_t* b) {
    asm volatile("mma.sync.aligned.m16n8k16.row.col.f32.f16.f16.f32 "
                 "{%0,%1,%2,%3}, {%4,%5,%6,%7}, {%8,%9}, {%0,%1,%2,%3};"
                 : "+f"(c[0]), "+f"(c[1]), "+f"(c[2]), "+f"(c[3])
                 : "r"(a[0]), "r"(a[1]), "r"(a[2]), "r"(a[3]), "r"(b[0]), "r"(b[1]));
}

__global__ __launch_bounds__(256, 2) void k_gemm_h(
    const __half* __restrict__ A, const __half* __restrict__ B,
    const float* __restrict__ bias, void* __restrict__ Cv,
    int M, int Nt, int out_half) {
    extern __shared__ char smem[];
    int tid = threadIdx.x;
    int wid = tid >> 5, lane = tid & 31;
    int wm = (wid >> 2) * 32;
    int wn = (wid & 3) * 32;
    int row0 = blockIdx.y * 64, col0 = blockIdx.x * 128;

    // A staging: row sr (0..63), 8-half group (16B); 1 uint4/thread
    int sr = tid >> 2;
    int sk = (tid & 3) * 8;
    int rowA = row0 + sr;
    bool aval = rowA < M;
    const __half* gA = A + (size_t)(aval ? rowA : 0) * 512 + sk;
    // B staging: k row bk (0..31), 16-half group (32B); 2 uint4/thread
    int bk = tid >> 3;
    int bn = (tid & 7) * 16;
    const __half* gB = B + (size_t)bk * Nt + col0 + bn;

    uint32_t ubase = (uint32_t)__cvta_generic_to_shared(smem);

    int aRow = wm + (lane & 15);
    int aCol = (lane >> 4) << 3;
    int kIdx = (lane & 7) + (((lane >> 3) & 1) << 3);
    int nOff = (lane >> 4) << 3;

    float acc[2][4][4];
#pragma unroll
    for (int i = 0; i < 2; i++)
#pragma unroll
        for (int j = 0; j < 4; j++)
#pragma unroll
            for (int k = 0; k < 4; k++) acc[i][j][k] = 0.f;

    // stage chunk 0 -> buffer 0
    {
        char* st = smem;
        uint4 va = aval ? __ldg((const uint4*)gA) : make_uint4(0, 0, 0, 0);
        *(uint4*)(st + O_AH + (sr * PADK + sk) * 2) = va;
        uint4 vb0 = __ldg((const uint4*)gB);
        uint4 vb1 = __ldg((const uint4*)gB + 1);
        *(uint4*)(st + O_BH + (bk * PADN + bn) * 2) = vb0;
        *(uint4*)(st + O_BH + (bk * PADN + bn) * 2 + 16) = vb1;
    }
    __syncthreads();

    for (int c = 0; c < 16; c++) {
        uint32_t ub = ubase + (c & 1) * STAGE_BYTES;

        // prefetch next chunk into registers
        uint4 pa, pb0, pb1;
        if (c < 15) {
            pa = aval ? __ldg((const uint4*)(gA + (c + 1) * 32)) : make_uint4(0, 0, 0, 0);
            const __half* nb = gB + (size_t)(c + 1) * 32 * Nt;
            pb0 = __ldg((const uint4*)nb);
            pb1 = __ldg((const uint4*)nb + 1);
        }

#pragma unroll
        for (int ks = 0; ks < 32; ks += 16) {
            uint32_t ah[2][4], bh[4][2];
#pragma unroll
            for (int mt = 0; mt < 2; mt++) {
                uint32_t off = ((uint32_t)((aRow + mt * 16) * PADK + ks + aCol)) * 2;
                ldm4(ah[mt], ub + O_AH + off);
            }
#pragma unroll
            for (int ntp = 0; ntp < 2; ntp++) {
                uint32_t off = ((uint32_t)((ks + kIdx) * PADN + wn + ntp * 16 + nOff)) * 2;
                uint32_t t[4];
                ldm4t(t, ub + O_BH + off);
                bh[ntp * 2][0] = t[0]; bh[ntp * 2][1] = t[1];
                bh[ntp * 2 + 1][0] = t[2]; bh[ntp * 2 + 1][1] = t[3];
            }
#pragma unroll
            for (int mt = 0; mt < 2; mt++)
#pragma unroll
                for (int nt = 0; nt < 4; nt++)
                    mma16816h(acc[mt][nt], ah[mt], bh[nt]);
        }

        if (c < 15) {
            char* st = smem + ((c & 1) ^ 1) * STAGE_BYTES;
            *(uint4*)(st + O_AH + (sr * PADK + sk) * 2) = pa;
            *(uint4*)(st + O_BH + (bk * PADN + bn) * 2) = pb0;
            *(uint4*)(st + O_BH + (bk * PADN + bn) * 2 + 16) = pb1;
        }
        __syncthreads();
    }

    // epilogue: bias + relu; fp16 or fp32 output
    int erow = row0 + wm + (lane >> 2);
    int ecol0 = col0 + wn + (lane & 3) * 2;
#pragma unroll
    for (int nt = 0; nt < 4; nt++) {
        int cc = ecol0 + nt * 8;
        float bx = __ldg(bias + cc), by = __ldg(bias + cc + 1);
#pragma unroll
        for (int mt = 0; mt < 2; mt++) {
            int r = erow + mt * 16;
#pragma unroll
            for (int hpart = 0; hpart < 2; hpart++) {
                int rr = r + hpart * 8;
                if (rr < M) {
                    float ox = fmaxf(acc[mt][nt][2 * hpart] + bx, 0.f);
                    float oy = fmaxf(acc[mt][nt][2 * hpart + 1] + by, 0.f);
                    if (out_half) {
                        __half2 h2 = __floats2half2_rn(ox, oy);
                        *(uint32_t*)((__half*)Cv + (size_t)rr * Nt + cc) = *(uint32_t*)&h2;
                    } else {
                        *(float2*)((float*)Cv + (size_t)rr * Nt + cc) = make_float2(ox, oy);
                    }
                }
            }
        }
    }
}

// ---------------- launch ----------------------------------------------------

extern "C" void kernel_launch(void* const* d_in, const int* in_sizes, int n_in,
                              void* d_out, int out_size) {
    const float* x    = (const float*)d_in[0];
    const int*   src0 = (const int*)d_in[1];
    const int*   dst0 = (const int*)d_in[2];
    const int*   src1 = (const int*)d_in[3];
    const int*   dst1 = (const int*)d_in[4];
    const float* W1   = (const float*)d_in[5];
    const float* b1   = (const float*)d_in[6];
    const float* W2   = (const float*)d_in[7];
    const float* b2   = (const float*)d_in[8];
    float* out = (float*)d_out;

    float* nrm;
    int *ints, *rpc, *col0, *col1, *part;
    __half *agg0h, *h1h, *agg1h, *w1h, *w2h;
    cudaGetSymbolAddress((void**)&nrm,   g_norm);
    cudaGetSymbolAddress((void**)&ints,  g_ints);
    cudaGetSymbolAddress((void**)&rpc,   g_rpc);
    cudaGetSymbolAddress((void**)&col0,  g_col0);
    cudaGetSymbolAddress((void**)&col1,  g_col1);
    cudaGetSymbolAddress((void**)&part,  g_part);
    cudaGetSymbolAddress((void**)&agg0h, g_agg0h);
    cudaGetSymbolAddress((void**)&h1h,   g_h1h);
    cudaGetSymbolAddress((void**)&agg1h, g_agg1h);
    cudaGetSymbolAddress((void**)&w1h,   g_w1h);
    cudaGetSymbolAddress((void**)&w2h,   g_w2h);

    cudaFuncSetAttribute(k_gemm_h, cudaFuncAttributeMaxDynamicSharedMemorySize, GSM_TOTAL);

    const float* din0  = nrm + OFF_C_DST0;
    const float* din1  = nrm + OFF_C_DST1;
    const float* outn0 = nrm + OFF_C_SRC0;
    const float* outn1 = nrm + OFF_C_SRC1;

    // 1) zero counters/cursors (no feature-buffer zero needed anymore)
    k_zeroi<<<256, 256>>>(ints, N_INTS);

    // 2) weight fp32->fp16 (independent; off critical path cost-wise)
    k_wprep<<<(512 * 256 + 256 * 256 + 255) / 256, 256>>>(W1, W2, w1h, w2h);

    // 3) degree counts
    k_count<<<(E0V + E1V + 255) / 256, 256>>>(src0, dst0, src1, dst1, ints);

    // 4) combined scan over [dst0 counts | dst1 counts] (24000)
    {
        int nb = (N_SCAN + 1023) / 1024;   // 24
        k_scan1<<<nb, 1024>>>(ints, rpc, part, N_SCAN);
        k_scan2<<<1, 128>>>(part, nb, rpc);
        k_scan3<<<nb, 1024>>>(rpc, part, N_SCAN);
    }

    // 5) fused norms + both CSC fills
    k_fill_norm<<<(E0V + E1V + 255) / 256, 256>>>(src0, dst0, src1, dst1,
                                                  rpc, ints, col0, col1, nrm);

    // 6) layer-1 gather: agg0h[d] = din0[d] * sum x[s]*outn0[s]  (fp16 out)
    k_gather0<<<(N_DST0 * 32 + 255) / 256, 256>>>(x, rpc, col0, outn0, din0,
                                                  agg0h, N_DST0);

    // 7) GEMM1: h1h = relu(agg0h @ W1h + b1)  (fp16 out)
    {
        dim3 grid(HID_F / 128, (N_DST0 + 63) / 64);   // (4, 313)
        k_gemm_h<<<grid, 256, GSM_TOTAL>>>(agg0h, w1h, b1, h1h, N_DST0, HID_F, 1);
    }

    // 8) layer-2 gather over fp16 h1
    k_gather1<<<(N_DST1 * 32 + 255) / 256, 256>>>(h1h, rpc + OFF_C_DST1, col1,
                                                  outn1, din1, agg1h, N_DST1);

    // 9) GEMM2: out = relu(agg1h @ W2h + b2)  (fp32 out)
    {
        dim3 grid(OUT_F / 128, (N_DST1 + 63) / 64);   // (2, 63)
        k_gemm_h<<<grid, 256, GSM_TOTAL>>>(agg1h, w2h, b2, out, N_DST1, OUT_F, 0);
    }
}

// round 12
// speedup vs baseline: 1.7092x; 1.0421x over previous
#include <cuda_runtime.h>
#include <cuda_fp16.h>
#include <cstdint>

#define N_SRC0 100000
#define N_DST0 20000
#define N_DST1 4000
#define E0V 640000
#define E1V 128000
#define IN_F 512
#define HID_F 512
#define OUT_F 256

// ---------------- scratch (device globals) ----------------------------------
__device__ __half g_xh[(size_t)N_SRC0 * IN_F];       // x * outn0, fp16 (102 MB)
__device__ __half g_agg0h[(size_t)N_DST0 * IN_F];
__device__ __half g_h1h[(size_t)N_DST0 * HID_F];     // relu(gemm1)*outn1, fp16
__device__ __half g_agg1h[(size_t)N_DST1 * HID_F];
__device__ __half g_w1h[512 * 512];
__device__ __half g_w2h[512 * 256];

// count layout: [C_DST0 (20000) | C_DST1 (4000) | C_SRC1 (20000) | C_SRC0 (100000)]
#define OFF_C_DST0 0
#define OFF_C_DST1 20000
#define OFF_C_SRC1 24000
#define OFF_C_SRC0 44000
#define N_CNT      144000
#define N_NORM     44000
#define OFF_CUR0   144000
#define OFF_CUR1   164000
#define N_INTS     168000
#define N_SCAN     24000
__device__ int g_ints[N_INTS];
__device__ float g_norm[N_NORM];    // din0 | din1 | outn1

__device__ int g_rpc[N_SCAN + 1];
__device__ int g_col0[E0V];
__device__ int g_col1[E1V];

// ---------------- utility kernels -------------------------------------------

__global__ void k_zeroi(int* __restrict__ b, int nb) {
    int stride = gridDim.x * blockDim.x;
    for (int i = blockIdx.x * blockDim.x + threadIdx.x; i < nb; i += stride)
        b[i] = 0;
}

__global__ void k_count(const int* __restrict__ s0, const int* __restrict__ d0,
                        const int* __restrict__ s1, const int* __restrict__ d1,
                        int* __restrict__ ints) {
    int i = blockIdx.x * blockDim.x + threadIdx.x;
    if (i < E0V) {
        atomicAdd(ints + OFF_C_SRC0 + s0[i], 1);
        atomicAdd(ints + OFF_C_DST0 + d0[i], 1);
    } else {
        int j = i - E0V;
        if (j < E1V) {
            atomicAdd(ints + OFF_C_SRC1 + s1[j], 1);
            atomicAdd(ints + OFF_C_DST1 + d1[j], 1);
        }
    }
}

// single-block scan over 24000 counts (1024 thr x 24 items)
__global__ void k_scan_one(const int* __restrict__ cnt, int* __restrict__ rp, int n) {
    __shared__ int ws[32];
    const int C = 24;
    int tid = threadIdx.x;
    int lane = tid & 31, warp = tid >> 5;
    int base = tid * C;
    int vals[C];
    int sum = 0;
#pragma unroll
    for (int j = 0; j < C; j++) {
        int idx = base + j;
        int v = (idx < n) ? cnt[idx] : 0;
        vals[j] = v;
        sum += v;
    }
    int s = sum;
#pragma unroll
    for (int d = 1; d < 32; d <<= 1) {
        int t = __shfl_up_sync(0xffffffffu, s, d);
        if (lane >= d) s += t;
    }
    if (lane == 31) ws[warp] = s;
    __syncthreads();
    if (warp == 0) {
        int w = ws[lane];
#pragma unroll
        for (int d = 1; d < 32; d <<= 1) {
            int t = __shfl_up_sync(0xffffffffu, w, d);
            if (lane >= d) w += t;
        }
        ws[lane] = w;
    }
    __syncthreads();
    int run = s - sum + (warp > 0 ? ws[warp - 1] : 0);   // exclusive prefix
    if (tid == 0) rp[0] = 0;
#pragma unroll
    for (int j = 0; j < C; j++) {
        int idx = base + j;
        run += vals[j];
        if (idx < n) rp[idx + 1] = run;
    }
}

// fused: norms (din0|din1|outn1) + both CSC fills
__global__ void k_fill_norm(const int* __restrict__ src0, const int* __restrict__ dst0,
                            const int* __restrict__ src1, const int* __restrict__ dst1,
                            const int* __restrict__ rpc, int* __restrict__ ints,
                            int* __restrict__ col0, int* __restrict__ col1,
                            float* __restrict__ nrm) {
    int i = blockIdx.x * blockDim.x + threadIdx.x;
    if (i < N_NORM) nrm[i] = rsqrtf(fmaxf((float)ints[i], 1.0f));
    if (i < E0V) {
        int k = dst0[i];
        int pos = rpc[k] + atomicAdd(ints + OFF_CUR0 + k, 1);
        col0[pos] = src0[i];
    } else {
        int j = i - E0V;
        if (j < E1V) {
            int k = dst1[j];
            int pos = rpc[OFF_C_DST1 + k] - E0V + atomicAdd(ints + OFF_CUR1 + k, 1);
            col1[pos] = src1[j];
        }
    }
}

// W fp32 -> fp16 (flat, both layers)
__global__ void k_wprep(const float* __restrict__ W1, const float* __restrict__ W2,
                        __half* __restrict__ w1h, __half* __restrict__ w2h) {
    int i = blockIdx.x * blockDim.x + threadIdx.x;   // float2 granularity
    if (i < 512 * 256) {
        float2 v = reinterpret_cast<const float2*>(W1)[i];
        reinterpret_cast<__half2*>(w1h)[i] = __floats2half2_rn(v.x, v.y);
    } else {
        int j = i - 512 * 256;
        if (j < 256 * 256) {
            float2 v = reinterpret_cast<const float2*>(W2)[j];
            reinterpret_cast<__half2*>(w2h)[j] = __floats2half2_rn(v.x, v.y);
        }
    }
}

// xh = x * rsqrt(max(outdeg0,1)), fp16. One float4 per thread.
__global__ void k_xprep(const float* __restrict__ x, const int* __restrict__ cnt,
                        __half* __restrict__ xh) {
    int i = blockIdx.x * blockDim.x + threadIdx.x;
    if (i >= N_SRC0 * (IN_F / 4)) return;
    int row = i >> 7;
    float sc = rsqrtf(fmaxf((float)__ldg(cnt + OFF_C_SRC0 + row), 1.0f));
    float4 v = reinterpret_cast<const float4*>(x)[i];
    __half2 h0 = __floats2half2_rn(v.x * sc, v.y * sc);
    __half2 h1 = __floats2half2_rn(v.z * sc, v.w * sc);
    reinterpret_cast<uint2*>(xh)[i] = make_uint2(*(uint32_t*)&h0, *(uint32_t*)&h1);
}

// ---------------- unified CSC gather: agg[d] = din[d] * sum_h rows ----------
// feature dim 512 fp16; warp per dst node; fp32 accumulation.
__global__ void k_gather_h(const __half* __restrict__ h,
                           const int* __restrict__ rp, const int* __restrict__ col,
                           const float* __restrict__ din,
                           __half* __restrict__ aggh, int n_dst, int ebase) {
    int w = (blockIdx.x * blockDim.x + threadIdx.x) >> 5;
    int lane = threadIdx.x & 31;
    if (w >= n_dst) return;
    int beg = rp[w] - ebase, end = rp[w + 1] - ebase;
    float acc[16];
#pragma unroll
    for (int i = 0; i < 16; i++) acc[i] = 0.f;
    for (int e = beg; e < end; e++) {
        int s = __ldg(col + e);
        const uint4* hp = reinterpret_cast<const uint4*>(h + (size_t)s * 512) + 2 * lane;
        uint4 p = __ldg(hp), q = __ldg(hp + 1);
        const uint32_t pr[8] = {p.x, p.y, p.z, p.w, q.x, q.y, q.z, q.w};
#pragma unroll
        for (int i = 0; i < 8; i++) {
            float2 f = __half22float2(*(const __half2*)&pr[i]);
            acc[2 * i] += f.x;
            acc[2 * i + 1] += f.y;
        }
    }
    float d = din[w];
    uint32_t o[8];
#pragma unroll
    for (int i = 0; i < 8; i++) {
        __half2 h2 = __floats2half2_rn(acc[2 * i] * d, acc[2 * i + 1] * d);
        o[i] = *(uint32_t*)&h2;
    }
    uint4* op = reinterpret_cast<uint4*>(aggh + (size_t)w * 512) + 2 * lane;
    op[0] = make_uint4(o[0], o[1], o[2], o[3]);
    op[1] = make_uint4(o[4], o[5], o[6], o[7]);
}

// ---------------- fp16 HMMA GEMM: C = rowscale * relu(A @ B + bias) ----------
#define PADK 40
#define PADN 136
#define SZ_A (64 * PADK * 2)
#define SZ_B (32 * PADN * 2)
#define STAGE_BYTES (SZ_A + SZ_B)          // 13824
#define GSM_TOTAL (2 * STAGE_BYTES)        // 27648
#define O_AH 0
#define O_BH SZ_A

__device__ __forceinline__ void ldm4(uint32_t* f, uint32_t addr) {
    asm volatile("ldmatrix.sync.aligned.m8n8.x4.shared.b16 {%0,%1,%2,%3}, [%4];"
                 : "=r"(f[0]), "=r"(f[1]), "=r"(f[2]), "=r"(f[3]) : "r"(addr));
}
__device__ __forceinline__ void ldm4t(uint32_t* f, uint32_t addr) {
    asm volatile("ldmatrix.sync.aligned.m8n8.x4.trans.shared.b16 {%0,%1,%2,%3}, [%4];"
                 : "=r"(f[0]), "=r"(f[1]), "=r"(f[2]), "=r"(f[3]) : "r"(addr));
}
__device__ __forceinline__ void mma16816h(float* c, const uint32_t* a, const uint32_t* b) {
    asm volatile("mma.sync.aligned.m16n8k16.row.col.f32.f16.f16.f32 "
                 "{%0,%1,%2,%3}, {%4,%5,%6,%7}, {%8,%9}, {%0,%1,%2,%3};"
                 : "+f"(c[0]), "+f"(c[1]), "+f"(c[2]), "+f"(c[3])
                 : "r"(a[0]), "r"(a[1]), "r"(a[2]), "r"(a[3]), "r"(b[0]), "r"(b[1]));
}

__global__ __launch_bounds__(256, 2) void k_gemm_h(
    const __half* __restrict__ A, const __half* __restrict__ B,
    const float* __restrict__ bias, const float* __restrict__ rscale,
    void* __restrict__ Cv, int M, int Nt, int out_half) {
    extern __shared__ char smem[];
    int tid = threadIdx.x;
    int wid = tid >> 5, lane = tid & 31;
    int wm = (wid >> 2) * 32;
    int wn = (wid & 3) * 32;
    int row0 = blockIdx.y * 64, col0 = blockIdx.x * 128;

    int sr = tid >> 2;
    int sk = (tid & 3) * 8;
    int rowA = row0 + sr;
    bool aval = rowA < M;
    const __half* gA = A + (size_t)(aval ? rowA : 0) * 512 + sk;
    int bk = tid >> 3;
    int bn = (tid & 7) * 16;
    const __half* gB = B + (size_t)bk * Nt + col0 + bn;

    uint32_t ubase = (uint32_t)__cvta_generic_to_shared(smem);

    int aRow = wm + (lane & 15);
    int aCol = (lane >> 4) << 3;
    int kIdx = (lane & 7) + (((lane >> 3) & 1) << 3);
    int nOff = (lane >> 4) << 3;

    float acc[2][4][4];
#pragma unroll
    for (int i = 0; i < 2; i++)
#pragma unroll
        for (int j = 0; j < 4; j++)
#pragma unroll
            for (int k = 0; k < 4; k++) acc[i][j][k] = 0.f;

    {
        char* st = smem;
        uint4 va = aval ? __ldg((const uint4*)gA) : make_uint4(0, 0, 0, 0);
        *(uint4*)(st + O_AH + (sr * PADK + sk) * 2) = va;
        uint4 vb0 = __ldg((const uint4*)gB);
        uint4 vb1 = __ldg((const uint4*)gB + 1);
        *(uint4*)(st + O_BH + (bk * PADN + bn) * 2) = vb0;
        *(uint4*)(st + O_BH + (bk * PADN + bn) * 2 + 16) = vb1;
    }
    __syncthreads();

    for (int c = 0; c < 16; c++) {
        uint32_t ub = ubase + (c & 1) * STAGE_BYTES;

        uint4 pa, pb0, pb1;
        if (c < 15) {
            pa = aval ? __ldg((const uint4*)(gA + (c + 1) * 32)) : make_uint4(0, 0, 0, 0);
            const __half* nb = gB + (size_t)(c + 1) * 32 * Nt;
            pb0 = __ldg((const uint4*)nb);
            pb1 = __ldg((const uint4*)nb + 1);
        }

#pragma unroll
        for (int ks = 0; ks < 32; ks += 16) {
            uint32_t ah[2][4], bh[4][2];
#pragma unroll
            for (int mt = 0; mt < 2; mt++) {
                uint32_t off = ((uint32_t)((aRow + mt * 16) * PADK + ks + aCol)) * 2;
                ldm4(ah[mt], ub + O_AH + off);
            }
#pragma unroll
            for (int ntp = 0; ntp < 2; ntp++) {
                uint32_t off = ((uint32_t)((ks + kIdx) * PADN + wn + ntp * 16 + nOff)) * 2;
                uint32_t t[4];
                ldm4t(t, ub + O_BH + off);
                bh[ntp * 2][0] = t[0]; bh[ntp * 2][1] = t[1];
                bh[ntp * 2 + 1][0] = t[2]; bh[ntp * 2 + 1][1] = t[3];
            }
#pragma unroll
            for (int mt = 0; mt < 2; mt++)
#pragma unroll
                for (int nt = 0; nt < 4; nt++)
                    mma16816h(acc[mt][nt], ah[mt], bh[nt]);
        }

        if (c < 15) {
            char* st = smem + ((c & 1) ^ 1) * STAGE_BYTES;
            *(uint4*)(st + O_AH + (sr * PADK + sk) * 2) = pa;
            *(uint4*)(st + O_BH + (bk * PADN + bn) * 2) = pb0;
            *(uint4*)(st + O_BH + (bk * PADN + bn) * 2 + 16) = pb1;
        }
        __syncthreads();
    }

    // epilogue: bias + relu (+ optional row scale); fp16 or fp32 out
    int erow = row0 + wm + (lane >> 2);
    int ecol0 = col0 + wn + (lane & 3) * 2;
#pragma unroll
    for (int nt = 0; nt < 4; nt++) {
        int cc = ecol0 + nt * 8;
        float bx = __ldg(bias + cc), by = __ldg(bias + cc + 1);
#pragma unroll
        for (int mt = 0; mt < 2; mt++) {
#pragma unroll
            for (int hpart = 0; hpart < 2; hpart++) {
                int rr = erow + mt * 16 + hpart * 8;
                if (rr < M) {
                    float rs = rscale ? __ldg(rscale + rr) : 1.0f;
                    float ox = fmaxf(acc[mt][nt][2 * hpart] + bx, 0.f) * rs;
                    float oy = fmaxf(acc[mt][nt][2 * hpart + 1] + by, 0.f) * rs;
                    if (out_half) {
                        __half2 h2 = __floats2half2_rn(ox, oy);
                        *(uint32_t*)((__half*)Cv + (size_t)rr * Nt + cc) = *(uint32_t*)&h2;
                    } else {
                        *(float2*)((float*)Cv + (size_t)rr * Nt + cc) = make_float2(ox, oy);
                    }
                }
            }
        }
    }
}

// ---------------- launch ----------------------------------------------------

extern "C" void kernel_launch(void* const* d_in, const int* in_sizes, int n_in,
                              void* d_out, int out_size) {
    const float* x    = (const float*)d_in[0];
    const int*   src0 = (const int*)d_in[1];
    const int*   dst0 = (const int*)d_in[2];
    const int*   src1 = (const int*)d_in[3];
    const int*   dst1 = (const int*)d_in[4];
    const float* W1   = (const float*)d_in[5];
    const float* b1   = (const float*)d_in[6];
    const float* W2   = (const float*)d_in[7];
    const float* b2   = (const float*)d_in[8];
    float* out = (float*)d_out;

    float* nrm;
    int *ints, *rpc, *col0, *col1;
    __half *xh, *agg0h, *h1h, *agg1h, *w1h, *w2h;
    cudaGetSymbolAddress((void**)&nrm,   g_norm);
    cudaGetSymbolAddress((void**)&ints,  g_ints);
    cudaGetSymbolAddress((void**)&rpc,   g_rpc);
    cudaGetSymbolAddress((void**)&col0,  g_col0);
    cudaGetSymbolAddress((void**)&col1,  g_col1);
    cudaGetSymbolAddress((void**)&xh,    g_xh);
    cudaGetSymbolAddress((void**)&agg0h, g_agg0h);
    cudaGetSymbolAddress((void**)&h1h,   g_h1h);
    cudaGetSymbolAddress((void**)&agg1h, g_agg1h);
    cudaGetSymbolAddress((void**)&w1h,   g_w1h);
    cudaGetSymbolAddress((void**)&w2h,   g_w2h);

    cudaFuncSetAttribute(k_gemm_h, cudaFuncAttributeMaxDynamicSharedMemorySize, GSM_TOTAL);

    const float* din0  = nrm + OFF_C_DST0;
    const float* din1  = nrm + OFF_C_DST1;
    const float* outn1 = nrm + OFF_C_SRC1;

    // 1) zero counters/cursors
    k_zeroi<<<256, 256>>>(ints, N_INTS);

    // 2) weight fp32->fp16
    k_wprep<<<(512 * 256 + 256 * 256 + 255) / 256, 256>>>(W1, W2, w1h, w2h);

    // 3) degree counts
    k_count<<<(E0V + E1V + 255) / 256, 256>>>(src0, dst0, src1, dst1, ints);

    // 4) xh = x * outn0 (fp16) — needs src0 counts
    k_xprep<<<(N_SRC0 * (IN_F / 4) + 255) / 256, 256>>>(x, ints, xh);

    // 5) single-block scan over [dst0|dst1] counts
    k_scan_one<<<1, 1024>>>(ints, rpc, N_SCAN);

    // 6) fused norms + both CSC fills
    k_fill_norm<<<(E0V + E1V + 255) / 256, 256>>>(src0, dst0, src1, dst1,
                                                  rpc, ints, col0, col1, nrm);

    // 7) layer-1 gather: agg0h[d] = din0[d] * sum xh[s]
    k_gather_h<<<(N_DST0 * 32 + 255) / 256, 256>>>(xh, rpc, col0, din0,
                                                   agg0h, N_DST0, 0);

    // 8) GEMM1: h1h = outn1[row] * relu(agg0h @ W1h + b1)  (fp16 out)
    {
        dim3 grid(HID_F / 128, (N_DST0 + 63) / 64);   // (4, 313)
        k_gemm_h<<<grid, 256, GSM_TOTAL>>>(agg0h, w1h, b1, outn1, h1h,
                                           N_DST0, HID_F, 1);
    }

    // 9) layer-2 gather: agg1h[d] = din1[d] * sum h1h[s]
    k_gather_h<<<(N_DST1 * 32 + 255) / 256, 256>>>(h1h, rpc + OFF_C_DST1, col1, din1,
                                                   agg1h, N_DST1, E0V);

    // 10) GEMM2: out = relu(agg1h @ W2h + b2)  (fp32 out)
    {
        dim3 grid(OUT_F / 128, (N_DST1 + 63) / 64);   // (2, 63)
        k_gemm_h<<<grid, 256, GSM_TOTAL>>>(agg1h, w2h, b2, nullptr, out,
                                           N_DST1, OUT_F, 0);
    }
}

// round 13
// speedup vs baseline: 1.8471x; 1.0807x over previous
#include <cuda_runtime.h>
#include <cuda_fp16.h>
#include <cstdint>

#define N_SRC0 100000
#define N_DST0 20000
#define N_DST1 4000
#define E0V 640000
#define E1V 128000
#define IN_F 512
#define HID_F 512
#define OUT_F 256

// ---------------- scratch (device globals) ----------------------------------
__device__ __half g_xh[(size_t)N_SRC0 * IN_F];       // x, fp16 (unscaled)
__device__ __half g_agg0h[(size_t)N_DST0 * IN_F];
__device__ __half g_h1h[(size_t)N_DST0 * HID_F];
__device__ __half g_agg1h[(size_t)N_DST1 * HID_F];
__device__ __half g_w1h[512 * 512];
__device__ __half g_w2h[512 * 256];

// count layout: [C_DST0 (20000) | C_DST1 (4000) | C_SRC1 (20000) | C_SRC0 (100000)]
#define OFF_C_DST0 0
#define OFF_C_DST1 20000
#define OFF_C_SRC1 24000
#define OFF_C_SRC0 44000
#define N_CNT      144000
#define OFF_CUR0   144000
#define OFF_CUR1   164000
#define N_INTS     168000
#define N_SCAN     24000
__device__ int g_ints[N_INTS];
__device__ float g_norm[N_CNT];     // din0 | din1 | outn1 | outn0

__device__ int g_rpc[N_SCAN + 1];
__device__ int g_col0[E0V];
__device__ int g_col1[E1V];

// ---------------- fused prep: x->fp16, W->fp16, degree counts ---------------
#define XP_BLOCKS 25000        // N_SRC0*IN_F/8 threads, 2 float4 each
#define WP_BLOCKS 192          // 49152 threads
#define CNT_BLOCKS 3000        // E0V+E1V threads

__global__ void k_zeroi(int* __restrict__ b, int nb) {
    int stride = gridDim.x * blockDim.x;
    for (int i = blockIdx.x * blockDim.x + threadIdx.x; i < nb; i += stride)
        b[i] = 0;
}

__device__ __forceinline__ uint4 cvt4(float4 v0, float4 v1) {
    __half2 h0 = __floats2half2_rn(v0.x, v0.y), h1 = __floats2half2_rn(v0.z, v0.w);
    __half2 h2 = __floats2half2_rn(v1.x, v1.y), h3 = __floats2half2_rn(v1.z, v1.w);
    return make_uint4(*(uint32_t*)&h0, *(uint32_t*)&h1,
                      *(uint32_t*)&h2, *(uint32_t*)&h3);
}

__global__ void k_prep(const float* __restrict__ x, __half* __restrict__ xh,
                       const float* __restrict__ W1, const float* __restrict__ W2,
                       __half* __restrict__ w1h, __half* __restrict__ w2h,
                       const int* __restrict__ s0, const int* __restrict__ d0,
                       const int* __restrict__ s1, const int* __restrict__ d1,
                       int* __restrict__ ints) {
    int b = blockIdx.x;
    if (b < XP_BLOCKS) {
        size_t i = (size_t)b * 256 + threadIdx.x;          // 2 float4 -> 1 uint4
        const float4* xp = reinterpret_cast<const float4*>(x) + 2 * i;
        reinterpret_cast<uint4*>(xh)[i] = cvt4(__ldg(xp), __ldg(xp + 1));
    } else if (b < XP_BLOCKS + WP_BLOCKS) {
        int i = (b - XP_BLOCKS) * 256 + threadIdx.x;
        if (i < 32768) {                                   // W1: 65536 float4
            const float4* wp = reinterpret_cast<const float4*>(W1) + 2 * i;
            reinterpret_cast<uint4*>(w1h)[i] = cvt4(__ldg(wp), __ldg(wp + 1));
        } else {                                           // W2: 32768 float4
            int j = i - 32768;
            const float4* wp = reinterpret_cast<const float4*>(W2) + 2 * j;
            reinterpret_cast<uint4*>(w2h)[j] = cvt4(__ldg(wp), __ldg(wp + 1));
        }
    } else {
        int i = (b - XP_BLOCKS - WP_BLOCKS) * 256 + threadIdx.x;
        if (i < E0V) {
            atomicAdd(ints + OFF_C_SRC0 + __ldg(s0 + i), 1);
            atomicAdd(ints + OFF_C_DST0 + __ldg(d0 + i), 1);
        } else {
            int j = i - E0V;
            if (j < E1V) {
                atomicAdd(ints + OFF_C_SRC1 + __ldg(s1 + j), 1);
                atomicAdd(ints + OFF_C_DST1 + __ldg(d1 + j), 1);
            }
        }
    }
}

// single-block scan over 24000 counts (1024 thr x 24 items)
__global__ void k_scan_one(const int* __restrict__ cnt, int* __restrict__ rp, int n) {
    __shared__ int ws[32];
    const int C = 24;
    int tid = threadIdx.x;
    int lane = tid & 31, warp = tid >> 5;
    int base = tid * C;
    int vals[C];
    int sum = 0;
#pragma unroll
    for (int j = 0; j < C; j++) {
        int idx = base + j;
        int v = (idx < n) ? cnt[idx] : 0;
        vals[j] = v;
        sum += v;
    }
    int s = sum;
#pragma unroll
    for (int d = 1; d < 32; d <<= 1) {
        int t = __shfl_up_sync(0xffffffffu, s, d);
        if (lane >= d) s += t;
    }
    if (lane == 31) ws[warp] = s;
    __syncthreads();
    if (warp == 0) {
        int w = ws[lane];
#pragma unroll
        for (int d = 1; d < 32; d <<= 1) {
            int t = __shfl_up_sync(0xffffffffu, w, d);
            if (lane >= d) w += t;
        }
        ws[lane] = w;
    }
    __syncthreads();
    int run = s - sum + (warp > 0 ? ws[warp - 1] : 0);
    if (tid == 0) rp[0] = 0;
#pragma unroll
    for (int j = 0; j < C; j++) {
        int idx = base + j;
        run += vals[j];
        if (idx < n) rp[idx + 1] = run;
    }
}

// fused: all norms + both CSC fills
__global__ void k_fill_norm(const int* __restrict__ src0, const int* __restrict__ dst0,
                            const int* __restrict__ src1, const int* __restrict__ dst1,
                            const int* __restrict__ rpc, int* __restrict__ ints,
                            int* __restrict__ col0, int* __restrict__ col1,
                            float* __restrict__ nrm) {
    int i = blockIdx.x * blockDim.x + threadIdx.x;
    if (i < N_CNT) nrm[i] = rsqrtf(fmaxf((float)ints[i], 1.0f));
    if (i < E0V) {
        int k = dst0[i];
        int pos = rpc[k] + atomicAdd(ints + OFF_CUR0 + k, 1);
        col0[pos] = src0[i];
    } else {
        int j = i - E0V;
        if (j < E1V) {
            int k = dst1[j];
            int pos = rpc[OFF_C_DST1 + k] - E0V + atomicAdd(ints + OFF_CUR1 + k, 1);
            col1[pos] = src1[j];
        }
    }
}

// ---------------- gather with per-edge scale (layer 1) ----------------------
// agg[d] = din[d] * sum_e escale[col[e]] * h[col[e]]; warp/dst; fp32 acc.
__global__ void k_gather_es(const __half* __restrict__ h,
                            const int* __restrict__ rp, const int* __restrict__ col,
                            const float* __restrict__ escale, const float* __restrict__ din,
                            __half* __restrict__ aggh, int n_dst) {
    int w = (blockIdx.x * blockDim.x + threadIdx.x) >> 5;
    int lane = threadIdx.x & 31;
    if (w >= n_dst) return;
    int beg = rp[w], end = rp[w + 1];
    float acc[16];
#pragma unroll
    for (int i = 0; i < 16; i++) acc[i] = 0.f;
    int e = beg;
    for (; e + 1 < end; e += 2) {
        int s0 = __ldg(col + e), s1 = __ldg(col + e + 1);
        float c0 = __ldg(escale + s0), c1 = __ldg(escale + s1);
        const uint4* hp0 = reinterpret_cast<const uint4*>(h + (size_t)s0 * 512) + 2 * lane;
        const uint4* hp1 = reinterpret_cast<const uint4*>(h + (size_t)s1 * 512) + 2 * lane;
        uint4 p0 = __ldg(hp0), q0 = __ldg(hp0 + 1);
        uint4 p1 = __ldg(hp1), q1 = __ldg(hp1 + 1);
        const uint32_t r0[8] = {p0.x, p0.y, p0.z, p0.w, q0.x, q0.y, q0.z, q0.w};
        const uint32_t r1[8] = {p1.x, p1.y, p1.z, p1.w, q1.x, q1.y, q1.z, q1.w};
#pragma unroll
        for (int i = 0; i < 8; i++) {
            float2 f0 = __half22float2(*(const __half2*)&r0[i]);
            float2 f1 = __half22float2(*(const __half2*)&r1[i]);
            acc[2 * i]     = fmaf(f0.x, c0, acc[2 * i]);
            acc[2 * i + 1] = fmaf(f0.y, c0, acc[2 * i + 1]);
            acc[2 * i]     = fmaf(f1.x, c1, acc[2 * i]);
            acc[2 * i + 1] = fmaf(f1.y, c1, acc[2 * i + 1]);
        }
    }
    if (e < end) {
        int s = __ldg(col + e);
        float c = __ldg(escale + s);
        const uint4* hp = reinterpret_cast<const uint4*>(h + (size_t)s * 512) + 2 * lane;
        uint4 p = __ldg(hp), q = __ldg(hp + 1);
        const uint32_t pr[8] = {p.x, p.y, p.z, p.w, q.x, q.y, q.z, q.w};
#pragma unroll
        for (int i = 0; i < 8; i++) {
            float2 f = __half22float2(*(const __half2*)&pr[i]);
            acc[2 * i]     = fmaf(f.x, c, acc[2 * i]);
            acc[2 * i + 1] = fmaf(f.y, c, acc[2 * i + 1]);
        }
    }
    float d = din[w];
    uint32_t o[8];
#pragma unroll
    for (int i = 0; i < 8; i++) {
        __half2 h2 = __floats2half2_rn(acc[2 * i] * d, acc[2 * i + 1] * d);
        o[i] = *(uint32_t*)&h2;
    }
    uint4* op = reinterpret_cast<uint4*>(aggh + (size_t)w * 512) + 2 * lane;
    op[0] = make_uint4(o[0], o[1], o[2], o[3]);
    op[1] = make_uint4(o[4], o[5], o[6], o[7]);
}

// ---------------- plain gather (layer 2; scale pre-folded into h rows) ------
__global__ void k_gather_ns(const __half* __restrict__ h,
                            const int* __restrict__ rp, const int* __restrict__ col,
                            const float* __restrict__ din,
                            __half* __restrict__ aggh, int n_dst, int ebase) {
    int w = (blockIdx.x * blockDim.x + threadIdx.x) >> 5;
    int lane = threadIdx.x & 31;
    if (w >= n_dst) return;
    int beg = rp[w] - ebase, end = rp[w + 1] - ebase;
    float acc[16];
#pragma unroll
    for (int i = 0; i < 16; i++) acc[i] = 0.f;
    for (int e = beg; e < end; e++) {
        int s = __ldg(col + e);
        const uint4* hp = reinterpret_cast<const uint4*>(h + (size_t)s * 512) + 2 * lane;
        uint4 p = __ldg(hp), q = __ldg(hp + 1);
        const uint32_t pr[8] = {p.x, p.y, p.z, p.w, q.x, q.y, q.z, q.w};
#pragma unroll
        for (int i = 0; i < 8; i++) {
            float2 f = __half22float2(*(const __half2*)&pr[i]);
            acc[2 * i] += f.x;
            acc[2 * i + 1] += f.y;
        }
    }
    float d = din[w];
    uint32_t o[8];
#pragma unroll
    for (int i = 0; i < 8; i++) {
        __half2 h2 = __floats2half2_rn(acc[2 * i] * d, acc[2 * i + 1] * d);
        o[i] = *(uint32_t*)&h2;
    }
    uint4* op = reinterpret_cast<uint4*>(aggh + (size_t)w * 512) + 2 * lane;
    op[0] = make_uint4(o[0], o[1], o[2], o[3]);
    op[1] = make_uint4(o[4], o[5], o[6], o[7]);
}

// ---------------- fp16 HMMA GEMM: C = rowscale * relu(A @ B + bias) ----------
#define PADK 40
#define PADN 136
#define SZ_A (64 * PADK * 2)
#define SZ_B (32 * PADN * 2)
#define STAGE_BYTES (SZ_A + SZ_B)
#define GSM_TOTAL (2 * STAGE_BYTES)
#define O_AH 0
#define O_BH SZ_A

__device__ __forceinline__ void ldm4(uint32_t* f, uint32_t addr) {
    asm volatile("ldmatrix.sync.aligned.m8n8.x4.shared.b16 {%0,%1,%2,%3}, [%4];"
                 : "=r"(f[0]), "=r"(f[1]), "=r"(f[2]), "=r"(f[3]) : "r"(addr));
}
__device__ __forceinline__ void ldm4t(uint32_t* f, uint32_t addr) {
    asm volatile("ldmatrix.sync.aligned.m8n8.x4.trans.shared.b16 {%0,%1,%2,%3}, [%4];"
                 : "=r"(f[0]), "=r"(f[1]), "=r"(f[2]), "=r"(f[3]) : "r"(addr));
}
__device__ __forceinline__ void mma16816h(float* c, const uint32_t* a, const uint32_t* b) {
    asm volatile("mma.sync.aligned.m16n8k16.row.col.f32.f16.f16.f32 "
                 "{%0,%1,%2,%3}, {%4,%5,%6,%7}, {%8,%9}, {%0,%1,%2,%3};"
                 : "+f"(c[0]), "+f"(c[1]), "+f"(c[2]), "+f"(c[3])
                 : "r"(a[0]), "r"(a[1]), "r"(a[2]), "r"(a[3]), "r"(b[0]), "r"(b[1]));
}

__global__ __launch_bounds__(256, 2) void k_gemm_h(
    const __half* __restrict__ A, const __half* __restrict__ B,
    const float* __restrict__ bias, const float* __restrict__ rscale,
    void* __restrict__ Cv, int M, int Nt, int out_half) {
    extern __shared__ char smem[];
    int tid = threadIdx.x;
    int wid = tid >> 5, lane = tid & 31;
    int wm = (wid >> 2) * 32;
    int wn = (wid & 3) * 32;
    int row0 = blockIdx.y * 64, col0 = blockIdx.x * 128;

    int sr = tid >> 2;
    int sk = (tid & 3) * 8;
    int rowA = row0 + sr;
    bool aval = rowA < M;
    const __half* gA = A + (size_t)(aval ? rowA : 0) * 512 + sk;
    int bk = tid >> 3;
    int bn = (tid & 7) * 16;
    const __half* gB = B + (size_t)bk * Nt + col0 + bn;

    uint32_t ubase = (uint32_t)__cvta_generic_to_shared(smem);

    int aRow = wm + (lane & 15);
    int aCol = (lane >> 4) << 3;
    int kIdx = (lane & 7) + (((lane >> 3) & 1) << 3);
    int nOff = (lane >> 4) << 3;

    float acc[2][4][4];
#pragma unroll
    for (int i = 0; i < 2; i++)
#pragma unroll
        for (int j = 0; j < 4; j++)
#pragma unroll
            for (int k = 0; k < 4; k++) acc[i][j][k] = 0.f;

    {
        char* st = smem;
        uint4 va = aval ? __ldg((const uint4*)gA) : make_uint4(0, 0, 0, 0);
        *(uint4*)(st + O_AH + (sr * PADK + sk) * 2) = va;
        uint4 vb0 = __ldg((const uint4*)gB);
        uint4 vb1 = __ldg((const uint4*)gB + 1);
        *(uint4*)(st + O_BH + (bk * PADN + bn) * 2) = vb0;
        *(uint4*)(st + O_BH + (bk * PADN + bn) * 2 + 16) = vb1;
    }
    __syncthreads();

    for (int c = 0; c < 16; c++) {
        uint32_t ub = ubase + (c & 1) * STAGE_BYTES;

        uint4 pa, pb0, pb1;
        if (c < 15) {
            pa = aval ? __ldg((const uint4*)(gA + (c + 1) * 32)) : make_uint4(0, 0, 0, 0);
            const __half* nb = gB + (size_t)(c + 1) * 32 * Nt;
            pb0 = __ldg((const uint4*)nb);
            pb1 = __ldg((const uint4*)nb + 1);
        }

#pragma unroll
        for (int ks = 0; ks < 32; ks += 16) {
            uint32_t ah[2][4], bh[4][2];
#pragma unroll
            for (int mt = 0; mt < 2; mt++) {
                uint32_t off = ((uint32_t)((aRow + mt * 16) * PADK + ks + aCol)) * 2;
                ldm4(ah[mt], ub + O_AH + off);
            }
#pragma unroll
            for (int ntp = 0; ntp < 2; ntp++) {
                uint32_t off = ((uint32_t)((ks + kIdx) * PADN + wn + ntp * 16 + nOff)) * 2;
                uint32_t t[4];
                ldm4t(t, ub + O_BH + off);
                bh[ntp * 2][0] = t[0]; bh[ntp * 2][1] = t[1];
                bh[ntp * 2 + 1][0] = t[2]; bh[ntp * 2 + 1][1] = t[3];
            }
#pragma unroll
            for (int mt = 0; mt < 2; mt++)
#pragma unroll
                for (int nt = 0; nt < 4; nt++)
                    mma16816h(acc[mt][nt], ah[mt], bh[nt]);
        }

        if (c < 15) {
            char* st = smem + ((c & 1) ^ 1) * STAGE_BYTES;
            *(uint4*)(st + O_AH + (sr * PADK + sk) * 2) = pa;
            *(uint4*)(st + O_BH + (bk * PADN + bn) * 2) = pb0;
            *(uint4*)(st + O_BH + (bk * PADN + bn) * 2 + 16) = pb1;
        }
        __syncthreads();
    }

    int erow = row0 + wm + (lane >> 2);
    int ecol0 = col0 + wn + (lane & 3) * 2;
#pragma unroll
    for (int nt = 0; nt < 4; nt++) {
        int cc = ecol0 + nt * 8;
        float bx = __ldg(bias + cc), by = __ldg(bias + cc + 1);
#pragma unroll
        for (int mt = 0; mt < 2; mt++) {
#pragma unroll
            for (int hpart = 0; hpart < 2; hpart++) {
                int rr = erow + mt * 16 + hpart * 8;
                if (rr < M) {
                    float rs = rscale ? __ldg(rscale + rr) : 1.0f;
                    float ox = fmaxf(acc[mt][nt][2 * hpart] + bx, 0.f) * rs;
                    float oy = fmaxf(acc[mt][nt][2 * hpart + 1] + by, 0.f) * rs;
                    if (out_half) {
                        __half2 h2 = __floats2half2_rn(ox, oy);
                        *(uint32_t*)((__half*)Cv + (size_t)rr * Nt + cc) = *(uint32_t*)&h2;
                    } else {
                        *(float2*)((float*)Cv + (size_t)rr * Nt + cc) = make_float2(ox, oy);
                    }
                }
            }
        }
    }
}

// ---------------- launch ----------------------------------------------------

extern "C" void kernel_launch(void* const* d_in, const int* in_sizes, int n_in,
                              void* d_out, int out_size) {
    const float* x    = (const float*)d_in[0];
    const int*   src0 = (const int*)d_in[1];
    const int*   dst0 = (const int*)d_in[2];
    const int*   src1 = (const int*)d_in[3];
    const int*   dst1 = (const int*)d_in[4];
    const float* W1   = (const float*)d_in[5];
    const float* b1   = (const float*)d_in[6];
    const float* W2   = (const float*)d_in[7];
    const float* b2   = (const float*)d_in[8];
    float* out = (float*)d_out;

    float* nrm;
    int *ints, *rpc, *col0, *col1;
    __half *xh, *agg0h, *h1h, *agg1h, *w1h, *w2h;
    cudaGetSymbolAddress((void**)&nrm,   g_norm);
    cudaGetSymbolAddress((void**)&ints,  g_ints);
    cudaGetSymbolAddress((void**)&rpc,   g_rpc);
    cudaGetSymbolAddress((void**)&col0,  g_col0);
    cudaGetSymbolAddress((void**)&col1,  g_col1);
    cudaGetSymbolAddress((void**)&xh,    g_xh);
    cudaGetSymbolAddress((void**)&agg0h, g_agg0h);
    cudaGetSymbolAddress((void**)&h1h,   g_h1h);
    cudaGetSymbolAddress((void**)&agg1h, g_agg1h);
    cudaGetSymbolAddress((void**)&w1h,   g_w1h);
    cudaGetSymbolAddress((void**)&w2h,   g_w2h);

    cudaFuncSetAttribute(k_gemm_h, cudaFuncAttributeMaxDynamicSharedMemorySize, GSM_TOTAL);

    const float* din0  = nrm + OFF_C_DST0;
    const float* din1  = nrm + OFF_C_DST1;
    const float* outn1 = nrm + OFF_C_SRC1;
    const float* outn0 = nrm + OFF_C_SRC0;

    // 1) zero counters/cursors
    k_zeroi<<<256, 256>>>(ints, N_INTS);

    // 2) fused prep: x->fp16 | W->fp16 | degree counts (independent jobs)
    k_prep<<<XP_BLOCKS + WP_BLOCKS + CNT_BLOCKS, 256>>>(x, xh, W1, W2, w1h, w2h,
                                                        src0, dst0, src1, dst1, ints);

    // 3) single-block scan over [dst0|dst1] counts
    k_scan_one<<<1, 1024>>>(ints, rpc, N_SCAN);

    // 4) fused norms + both CSC fills
    k_fill_norm<<<(E0V + E1V + 255) / 256, 256>>>(src0, dst0, src1, dst1,
                                                  rpc, ints, col0, col1, nrm);

    // 5) layer-1 gather: agg0h[d] = din0[d] * sum outn0[s]*xh[s]
    k_gather_es<<<(N_DST0 * 32 + 255) / 256, 256>>>(xh, rpc, col0, outn0, din0,
                                                    agg0h, N_DST0);

    // 6) GEMM1: h1h = outn1[row] * relu(agg0h @ W1h + b1)  (fp16 out)
    {
        dim3 grid(HID_F / 128, (N_DST0 + 63) / 64);
        k_gemm_h<<<grid, 256, GSM_TOTAL>>>(agg0h, w1h, b1, outn1, h1h,
                                           N_DST0, HID_F, 1);
    }

    // 7) layer-2 gather: agg1h[d] = din1[d] * sum h1h[s]
    k_gather_ns<<<(N_DST1 * 32 + 255) / 256, 256>>>(h1h, rpc + OFF_C_DST1, col1, din1,
                                                    agg1h, N_DST1, E0V);

    // 8) GEMM2: out = relu(agg1h @ W2h + b2)  (fp32 out)
    {
        dim3 grid(OUT_F / 128, (N_DST1 + 63) / 64);
        k_gemm_h<<<grid, 256, GSM_TOTAL>>>(agg1h, w2h, b2, nullptr, out,
                                           N_DST1, OUT_F, 0);
    }
}